// round 7
// baseline (speedup 1.0000x reference)
#include <cuda_runtime.h>
#include <cuda_fp16.h>
#include <cstdint>
#include <math.h>

// ---- Problem constants ----
#define BDIM 2048
#define DDIM 1024
#define UDIM 1024
#define NB   8
#define KACT 9216
#define NCOMB 4096

// ---- Scratch (device globals; no allocation allowed) ----
__device__ __half g_xh[BDIM * 2048];               // [x | h_prev] fp16
__device__ float  g_z[BDIM * 4096];                // LSTM preacts fp32
__device__ __half g_act[(size_t)BDIM * KACT];      // [silu | bases] fp16
__device__ __half g_comb[(size_t)BDIM * NCOMB];    // [h | kan0..2] fp16
__device__ __half g_wl[(size_t)2048 * 4096];       // fused [Wk;Wr]
__device__ __half g_wk[(size_t)KACT * 3072];       // fused KAN weights
__device__ __half g_wc[(size_t)4096 * 1024];       // combine weights

// ---- PTX helpers ----
__device__ __forceinline__ uint32_t smem_u32(const void* p) {
    uint32_t a;
    asm("{ .reg .u64 t; cvta.to.shared.u64 t, %1; cvt.u32.u64 %0, t; }"
        : "=r"(a) : "l"(p));
    return a;
}
__device__ __forceinline__ void cp16(uint32_t s, const void* g) {
    asm volatile("cp.async.cg.shared.global [%0], [%1], 16;" :: "r"(s), "l"(g));
}
__device__ __forceinline__ void cp_commit() {
    asm volatile("cp.async.commit_group;" ::: "memory");
}
template<int N> __device__ __forceinline__ void cp_wait() {
    asm volatile("cp.async.wait_group %0;" :: "n"(N) : "memory");
}
__device__ __forceinline__ void ldmA(uint32_t* r, uint32_t a) {
    asm volatile("ldmatrix.sync.aligned.m8n8.x4.shared.b16 {%0,%1,%2,%3}, [%4];"
                 : "=r"(r[0]), "=r"(r[1]), "=r"(r[2]), "=r"(r[3]) : "r"(a));
}
__device__ __forceinline__ void ldmBT(uint32_t* r, uint32_t a) {
    asm volatile("ldmatrix.sync.aligned.m8n8.x4.trans.shared.b16 {%0,%1,%2,%3}, [%4];"
                 : "=r"(r[0]), "=r"(r[1]), "=r"(r[2]), "=r"(r[3]) : "r"(a));
}
__device__ __forceinline__ void mma16(float* c, const uint32_t* a, const uint32_t* b) {
    asm volatile(
        "mma.sync.aligned.m16n8k16.row.col.f32.f16.f16.f32 "
        "{%0,%1,%2,%3}, {%4,%5,%6,%7}, {%8,%9}, {%0,%1,%2,%3};"
        : "+f"(c[0]), "+f"(c[1]), "+f"(c[2]), "+f"(c[3])
        : "r"(a[0]), "r"(a[1]), "r"(a[2]), "r"(a[3]), "r"(b[0]), "r"(b[1]));
}

// =====================================================================
// FP16 mma.sync GEMM: BMxBN=128 CTA tile, BM in {128,256}.
// THREADS = BM*2 (8 or 16 warps, col-major 4-wide warp grid),
// warp tile 64x32, BK=64, 3-stage cp.async.
// COUT: 0 = fp32 C (+bias), 1 = fp16 C.
// =====================================================================
#define BKH 64
#define HSSTG 3

extern __shared__ char smem_h[];

__device__ __forceinline__ uint32_t offA(int r, int c) {
    return (uint32_t)(r * 128 + ((c ^ (r & 7)) << 4));
}
__device__ __forceinline__ uint32_t offB(int k, int c) {
    return (uint32_t)(k * 256 + ((c ^ (k & 7)) << 4));
}

template<int BM, int COUT>
__global__ __launch_bounds__(BM * 2, 256 / BM) void gemm_h(
    const __half* __restrict__ A, int lda,
    const __half* __restrict__ B, int ldb,
    const float* __restrict__ bias,
    void* __restrict__ Cv, int ldc, int colOff, int K)
{
    constexpr int THREADS = BM * 2;
    constexpr int HAB = BM * 128;            // A tile bytes/stage
    constexpr int STG = HAB + 16384;         // + B tile

    const int tid = threadIdx.x;
    const int lane = tid & 31;
    const int w = tid >> 5;
    const int rowBase = blockIdx.y * BM;
    const int colBase = blockIdx.x * 128;

    const uint32_t sb = smem_u32(smem_h);

    float acc[4][4][4];
#pragma unroll
    for (int i = 0; i < 4; i++)
#pragma unroll
        for (int j = 0; j < 4; j++)
#pragma unroll
            for (int q = 0; q < 4; q++) acc[i][j][q] = 0.0f;

    const int nk = K / BKH;

    auto load_stage = [&](int t, int s) {
        const int kBase = t * BKH;
        const uint32_t sA = sb + s * STG;
        const uint32_t sB = sA + HAB;
#pragma unroll
        for (int i = 0; i < (BM * 8) / THREADS; i++) {   // A chunks
            int idx = i * THREADS + tid;
            int r = idx >> 3, c = idx & 7;
            cp16(sA + offA(r, c), A + (size_t)(rowBase + r) * lda + kBase + c * 8);
        }
#pragma unroll
        for (int i = 0; i < 1024 / THREADS; i++) {       // B chunks
            int idx = i * THREADS + tid;
            int r = idx >> 4, c = idx & 15;
            cp16(sB + offB(r, c), B + (size_t)(kBase + r) * ldb + colBase + c * 8);
        }
    };

#pragma unroll
    for (int s = 0; s < HSSTG - 1; s++) { load_stage(s, s); cp_commit(); }

    const int wm = (w >> 2) * 64;
    const int wn = (w & 3) * 32;
    const int gid = lane >> 2;
    const int tg  = lane & 3;
    const int aRow = lane & 15;
    const int aSel = lane >> 4;
    const int bRow = lane & 15;
    const int bSel = lane >> 4;

    for (int t = 0; t < nk; t++) {
        cp_wait<HSSTG - 2>();
        __syncthreads();
        const int tn = t + HSSTG - 1;
        if (tn < nk) load_stage(tn, tn % HSSTG);
        cp_commit();

        const uint32_t sA = sb + (t % HSSTG) * STG;
        const uint32_t sB = sA + HAB;

#pragma unroll
        for (int ks = 0; ks < 4; ks++) {
            uint32_t af[4][4], bf[4][2];
#pragma unroll
            for (int i = 0; i < 4; i++)
                ldmA(af[i], sA + offA(wm + i * 16 + aRow, 2 * ks + aSel));
#pragma unroll
            for (int j2 = 0; j2 < 2; j2++) {
                uint32_t r4[4];
                ldmBT(r4, sB + offB(ks * 16 + bRow, (w & 3) * 4 + j2 * 2 + bSel));
                bf[2 * j2][0] = r4[0]; bf[2 * j2][1] = r4[1];
                bf[2 * j2 + 1][0] = r4[2]; bf[2 * j2 + 1][1] = r4[3];
            }
#pragma unroll
            for (int i = 0; i < 4; i++)
#pragma unroll
                for (int j = 0; j < 4; j++)
                    mma16(acc[i][j], af[i], bf[j]);
        }
    }

    // ---- epilogue ----
#pragma unroll
    for (int i = 0; i < 4; i++) {
        const int r0 = rowBase + wm + i * 16 + gid;
#pragma unroll
        for (int j = 0; j < 4; j++) {
            const int cn = colBase + wn + j * 8 + 2 * tg;
            float v0 = acc[i][j][0], v1 = acc[i][j][1];
            float v2 = acc[i][j][2], v3 = acc[i][j][3];
            if (COUT == 0 && bias) {
                v0 += bias[cn]; v1 += bias[cn + 1];
                v2 += bias[cn]; v3 += bias[cn + 1];
            }
            if (COUT == 0) {
                float* C = (float*)Cv;
                float2 p0; p0.x = v0; p0.y = v1;
                float2 p1; p1.x = v2; p1.y = v3;
                *(float2*)(C + (size_t)r0 * ldc + colOff + cn) = p0;
                *(float2*)(C + (size_t)(r0 + 8) * ldc + colOff + cn) = p1;
            } else {
                __half* C = (__half*)Cv;
                *(__half2*)(C + (size_t)r0 * ldc + colOff + cn) = __floats2half2_rn(v0, v1);
                *(__half2*)(C + (size_t)(r0 + 8) * ldc + colOff + cn) = __floats2half2_rn(v2, v3);
            }
        }
    }
}

// =====================================================================
// Weight conversion (fp32 -> fp16, pre-fused layouts)
// =====================================================================
__global__ void cvt_lstm(const float* __restrict__ wk, const float* __restrict__ wr,
                         __half* __restrict__ o)
{
    long e = ((long)blockIdx.x * 256 + threadIdx.x) * 8;
    int r = (int)(e >> 12), n = (int)(e & 4095);
    const float* s = (r < 1024) ? wk + (size_t)r * 4096 + n
                                : wr + (size_t)(r - 1024) * 4096 + n;
    float4 v0 = *(const float4*)s;
    float4 v1 = *(const float4*)(s + 4);
    __half2 h[4];
    h[0] = __floats2half2_rn(v0.x, v0.y);
    h[1] = __floats2half2_rn(v0.z, v0.w);
    h[2] = __floats2half2_rn(v1.x, v1.y);
    h[3] = __floats2half2_rn(v1.z, v1.w);
    *(uint4*)(o + e) = *(uint4*)h;
}

__global__ void cvt_kan(const float* __restrict__ bw, const float* __restrict__ sw,
                        __half* __restrict__ o)
{
    int col = (blockIdx.x * 128 + threadIdx.x) * 8;   // grid.x = 3
    int k = blockIdx.y;
    int l = col >> 10, u = col & 1023;
    const float* s = (k < 1024)
        ? bw + ((size_t)l * 1024 + k) * 1024 + u
        : sw + ((size_t)l * 8192 + (k - 1024)) * 1024 + u;
    float4 v0 = *(const float4*)s;
    float4 v1 = *(const float4*)(s + 4);
    __half2 h[4];
    h[0] = __floats2half2_rn(v0.x, v0.y);
    h[1] = __floats2half2_rn(v0.z, v0.w);
    h[2] = __floats2half2_rn(v1.x, v1.y);
    h[3] = __floats2half2_rn(v1.z, v1.w);
    *(uint4*)(o + (size_t)k * 3072 + col) = *(uint4*)h;
}

__global__ void cvt_comb(const float* __restrict__ wc, __half* __restrict__ o)
{
    long e = ((long)blockIdx.x * 256 + threadIdx.x) * 8;
    float4 v0 = *(const float4*)(wc + e);
    float4 v1 = *(const float4*)(wc + e + 4);
    __half2 h[4];
    h[0] = __floats2half2_rn(v0.x, v0.y);
    h[1] = __floats2half2_rn(v0.z, v0.w);
    h[2] = __floats2half2_rn(v1.x, v1.y);
    h[3] = __floats2half2_rn(v1.z, v1.w);
    *(uint4*)(o + e) = *(uint4*)h;
}

// =====================================================================
// Elementwise producers
// =====================================================================
__global__ void concat_xh_kernel(const float* __restrict__ x,
                                 const float* __restrict__ h,
                                 __half* __restrict__ xh)
{
    int i = blockIdx.x * 256 + threadIdx.x;
    long e = (long)i * 8;
    int b = (int)(e >> 11), c = (int)(e & 2047);
    const float* src = (c < 1024) ? x + (size_t)b * 1024 + c
                                  : h + (size_t)b * 1024 + (c - 1024);
    float4 v0 = *(const float4*)src;
    float4 v1 = *(const float4*)(src + 4);
    __half2 o[4];
    o[0] = __floats2half2_rn(v0.x, v0.y);
    o[1] = __floats2half2_rn(v0.z, v0.w);
    o[2] = __floats2half2_rn(v1.x, v1.y);
    o[3] = __floats2half2_rn(v1.z, v1.w);
    *(uint4*)(xh + e) = *(uint4*)o;
}

__global__ void lstm_gates_kernel(const float* __restrict__ z,
                                  const float* __restrict__ bias,
                                  const float* __restrict__ c_prev,
                                  float* __restrict__ out_h,
                                  float* __restrict__ out_c,
                                  __half* __restrict__ comb)
{
    int i = blockIdx.x * blockDim.x + threadIdx.x;
    if (i >= BDIM * UDIM) return;
    int b = i / UDIM, u = i - b * UDIM;
    const float* zr = z + (size_t)b * 4 * UDIM;
    float zi = zr[u]            + bias[u];
    float zf = zr[UDIM + u]     + bias[UDIM + u];
    float zg = zr[2 * UDIM + u] + bias[2 * UDIM + u];
    float zo = zr[3 * UDIM + u] + bias[3 * UDIM + u];
    float si = 1.0f / (1.0f + expf(-zi));
    float sf = 1.0f / (1.0f + expf(-zf));
    float so = 1.0f / (1.0f + expf(-zo));
    float c = sf * c_prev[i] + si * tanhf(zg);
    float h = so * tanhf(c);
    out_h[i] = h;
    out_c[i] = c;
    comb[(size_t)b * NCOMB + u] = __float2half(h);
}

__device__ __forceinline__ float knot(int j) {
    return (float)(-1.0 + (2.0 / 5.0) * (double)(j - 3));
}
__global__ void act_kernel(const float* __restrict__ x, __half* __restrict__ act)
{
    int i = blockIdx.x * blockDim.x + threadIdx.x;
    if (i >= BDIM * DDIM) return;
    int b = i / DDIM, d = i - b * DDIM;
    float xv = x[i];
    float s = xv / (1.0f + expf(-xv));

    float bb[11];
#pragma unroll
    for (int j = 0; j < 11; j++)
        bb[j] = (xv >= knot(j) && xv < knot(j + 1)) ? 1.0f : 0.0f;
#pragma unroll
    for (int p = 1; p <= 3; p++) {
#pragma unroll
        for (int j = 0; j <= 10 - p; j++) {
            float tj  = knot(j),     tjp  = knot(j + p);
            float tj1 = knot(j + 1), tjp1 = knot(j + p + 1);
            bb[j] = (xv - tj) / (tjp - tj) * bb[j]
                  + (tjp1 - xv) / (tjp1 - tj1) * bb[j + 1];
        }
    }
    __half* row = act + (size_t)b * KACT;
    row[d] = __float2half(s);
    __half2 o[4];
    o[0] = __floats2half2_rn(bb[0], bb[1]);
    o[1] = __floats2half2_rn(bb[2], bb[3]);
    o[2] = __floats2half2_rn(bb[4], bb[5]);
    o[3] = __floats2half2_rn(bb[6], bb[7]);
    *(uint4*)(row + DDIM + d * NB) = *(uint4*)o;
}

// =====================================================================
// Launch
// =====================================================================
extern "C" void kernel_launch(void* const* d_in, const int* in_sizes, int n_in,
                              void* d_out, int out_size)
{
    const float* x       = (const float*)d_in[0];
    const float* h_prev  = (const float*)d_in[1];
    const float* c_prev  = (const float*)d_in[2];
    const float* lstm_k  = (const float*)d_in[3];
    const float* lstm_rk = (const float*)d_in[4];
    const float* lstm_b  = (const float*)d_in[5];
    const float* kan_bw  = (const float*)d_in[6];
    const float* kan_sw  = (const float*)d_in[7];
    const float* comb_w  = (const float*)d_in[8];
    const float* comb_b  = (const float*)d_in[9];

    float* out   = (float*)d_out;
    float* out_h = out + (size_t)BDIM * UDIM;
    float* out_c = out + (size_t)2 * BDIM * UDIM;

    __half *xh, *act, *comb, *wl, *wk, *wc;
    float* z;
    cudaGetSymbolAddress((void**)&xh,   g_xh);
    cudaGetSymbolAddress((void**)&z,    g_z);
    cudaGetSymbolAddress((void**)&act,  g_act);
    cudaGetSymbolAddress((void**)&comb, g_comb);
    cudaGetSymbolAddress((void**)&wl,   g_wl);
    cudaGetSymbolAddress((void**)&wk,   g_wk);
    cudaGetSymbolAddress((void**)&wc,   g_wc);

    const int DYN128 = HSSTG * (128 * 128 + 16384);   // 98304
    const int DYN256 = HSSTG * (256 * 128 + 16384);   // 147456
    cudaFuncSetAttribute(gemm_h<128, 0>, cudaFuncAttributeMaxDynamicSharedMemorySize, DYN128);
    cudaFuncSetAttribute(gemm_h<256, 0>, cudaFuncAttributeMaxDynamicSharedMemorySize, DYN256);
    cudaFuncSetAttribute(gemm_h<256, 1>, cudaFuncAttributeMaxDynamicSharedMemorySize, DYN256);

    // Weight conversion / fusion
    cvt_lstm<<<2048 * 4096 / 8 / 256, 256>>>(lstm_k, lstm_rk, wl);
    cvt_kan<<<dim3(3, KACT), 128>>>(kan_bw, kan_sw, wk);
    cvt_comb<<<4096 * 1024 / 8 / 256, 256>>>(comb_w, wc);

    // Activation producers
    concat_xh_kernel<<<BDIM * 2048 / 8 / 256, 256>>>(x, h_prev, xh);
    act_kernel<<<(BDIM * DDIM + 255) / 256, 256>>>(x, act);

    // LSTM GEMM: z = [x|h] @ [Wk;Wr]  (fp32 out), BM=256
    gemm_h<256, 0><<<dim3(4096 / 128, BDIM / 256), 512, DYN256>>>(
        xh, 2048, wl, 4096, nullptr, z, 4096, 0, 2048);

    // Gates
    lstm_gates_kernel<<<(BDIM * UDIM + 255) / 256, 256>>>(
        z, lstm_b, c_prev, out_h, out_c, comb);

    // KAN (3 layers fused, N=3072) -> comb[:, 1024+n] (fp16 out), BM=256
    gemm_h<256, 1><<<dim3(3072 / 128, BDIM / 256), 512, DYN256>>>(
        act, KACT, wk, 3072, nullptr, comb, NCOMB, 1024, KACT);

    // Combine: out = comb @ Wc + b (fp32 out), BM=128
    gemm_h<128, 0><<<dim3(1024 / 128, BDIM / 128), 256, DYN128>>>(
        comb, NCOMB, wc, 1024, comb_b, out, 1024, 0, 4096);
}

// round 8
// speedup vs baseline: 1.4531x; 1.4531x over previous
#include <cuda_runtime.h>
#include <cuda_fp16.h>
#include <cstdint>
#include <math.h>

// ---- Problem constants ----
#define BDIM 2048
#define DDIM 1024
#define UDIM 1024
#define NB   8
#define KACT 9216
#define NCOMB 4096

// ---- Scratch (device globals; no allocation allowed) ----
__device__ __half g_xh[BDIM * 2048];               // [x | h_prev] fp16
__device__ float  g_z[BDIM * 4096];                // LSTM preacts; later combine partials
__device__ __half g_act[(size_t)BDIM * KACT];      // [silu | bases] fp16
__device__ __half g_comb[(size_t)BDIM * NCOMB];    // [h | kan0..2] fp16
__device__ __half g_wl[(size_t)2048 * 4096];       // fused [Wk;Wr]
__device__ __half g_wk[(size_t)KACT * 3072];       // fused KAN weights
__device__ __half g_wc[(size_t)4096 * 1024];       // combine weights

// ---- PTX helpers ----
__device__ __forceinline__ uint32_t smem_u32(const void* p) {
    uint32_t a;
    asm("{ .reg .u64 t; cvta.to.shared.u64 t, %1; cvt.u32.u64 %0, t; }"
        : "=r"(a) : "l"(p));
    return a;
}
__device__ __forceinline__ void cp16(uint32_t s, const void* g) {
    asm volatile("cp.async.cg.shared.global [%0], [%1], 16;" :: "r"(s), "l"(g));
}
__device__ __forceinline__ void cp_commit() {
    asm volatile("cp.async.commit_group;" ::: "memory");
}
template<int N> __device__ __forceinline__ void cp_wait() {
    asm volatile("cp.async.wait_group %0;" :: "n"(N) : "memory");
}
__device__ __forceinline__ void ldmA(uint32_t* r, uint32_t a) {
    asm volatile("ldmatrix.sync.aligned.m8n8.x4.shared.b16 {%0,%1,%2,%3}, [%4];"
                 : "=r"(r[0]), "=r"(r[1]), "=r"(r[2]), "=r"(r[3]) : "r"(a));
}
__device__ __forceinline__ void ldmBT(uint32_t* r, uint32_t a) {
    asm volatile("ldmatrix.sync.aligned.m8n8.x4.trans.shared.b16 {%0,%1,%2,%3}, [%4];"
                 : "=r"(r[0]), "=r"(r[1]), "=r"(r[2]), "=r"(r[3]) : "r"(a));
}
__device__ __forceinline__ void mma16(float* c, const uint32_t* a, const uint32_t* b) {
    asm volatile(
        "mma.sync.aligned.m16n8k16.row.col.f32.f16.f16.f32 "
        "{%0,%1,%2,%3}, {%4,%5,%6,%7}, {%8,%9}, {%0,%1,%2,%3};"
        : "+f"(c[0]), "+f"(c[1]), "+f"(c[2]), "+f"(c[3])
        : "r"(a[0]), "r"(a[1]), "r"(a[2]), "r"(a[3]), "r"(b[0]), "r"(b[1]));
}

#define BKH 64
#define HAB 16384
#define HSTG 32768
#define HSSTG 3

extern __shared__ char smem_h[];

__device__ __forceinline__ uint32_t offA(int r, int c) {
    return (uint32_t)(r * 128 + ((c ^ (r & 7)) << 4));
}
__device__ __forceinline__ uint32_t offB(int k, int c) {
    return (uint32_t)(k * 256 + ((c ^ (k & 7)) << 4));
}

// =====================================================================
// Fused LSTM+KAN GEMM launch. 896 CTAs:
//   bid <  384 : KAN  tile  (A=act  K=9216, B=wk ldb=3072, fp16 out -> comb)
//   bid >= 384 : LSTM tile  (A=xh   K=2048, B=wl ldb=4096, fp32 out -> z)
// Mainloop identical to round-4 gemm_h.
// =====================================================================
__global__ __launch_bounds__(256, 2) void gemm_fused(
    const __half* __restrict__ actp, const __half* __restrict__ wkp,
    const __half* __restrict__ xhp,  const __half* __restrict__ wlp,
    __half* __restrict__ comb, float* __restrict__ z)
{
    const int bid = blockIdx.x;
    const bool isKan = bid < 384;
    const __half *A, *B;
    int lda, ldb, K, rowBase, colBase;
    if (isKan) {
        A = actp; B = wkp; lda = KACT; ldb = 3072; K = KACT;
        colBase = (bid % 24) * 128; rowBase = (bid / 24) * 128;
    } else {
        int b2 = bid - 384;
        A = xhp; B = wlp; lda = 2048; ldb = 4096; K = 2048;
        colBase = (b2 % 32) * 128; rowBase = (b2 / 32) * 128;
    }

    const int tid = threadIdx.x;
    const int lane = tid & 31;
    const int w = tid >> 5;
    const uint32_t sb = smem_u32(smem_h);

    float acc[4][4][4];
#pragma unroll
    for (int i = 0; i < 4; i++)
#pragma unroll
        for (int j = 0; j < 4; j++)
#pragma unroll
            for (int q = 0; q < 4; q++) acc[i][j][q] = 0.0f;

    const int nk = K / BKH;

    auto load_stage = [&](int t, int s) {
        const int kBase = t * BKH;
        const uint32_t sA = sb + s * HSTG;
        const uint32_t sB = sA + HAB;
#pragma unroll
        for (int i = 0; i < 4; i++) {
            int idx = i * 256 + tid;
            int r = idx >> 3, c = idx & 7;
            cp16(sA + offA(r, c), A + (size_t)(rowBase + r) * lda + kBase + c * 8);
        }
#pragma unroll
        for (int i = 0; i < 4; i++) {
            int idx = i * 256 + tid;
            int r = idx >> 4, c = idx & 15;
            cp16(sB + offB(r, c), B + (size_t)(kBase + r) * ldb + colBase + c * 8);
        }
    };

#pragma unroll
    for (int s = 0; s < HSSTG - 1; s++) { load_stage(s, s); cp_commit(); }

    const int wm = (w >> 2) * 64;
    const int wn = (w & 3) * 32;
    const int gid = lane >> 2;
    const int tg  = lane & 3;
    const int aRow = lane & 15;
    const int aSel = lane >> 4;
    const int bRow = lane & 15;
    const int bSel = lane >> 4;

    for (int t = 0; t < nk; t++) {
        cp_wait<HSSTG - 2>();
        __syncthreads();
        const int tn = t + HSSTG - 1;
        if (tn < nk) load_stage(tn, tn % HSSTG);
        cp_commit();

        const uint32_t sA = sb + (t % HSSTG) * HSTG;
        const uint32_t sB = sA + HAB;

#pragma unroll
        for (int ks = 0; ks < 4; ks++) {
            uint32_t af[4][4], bf[4][2];
#pragma unroll
            for (int i = 0; i < 4; i++)
                ldmA(af[i], sA + offA(wm + i * 16 + aRow, 2 * ks + aSel));
#pragma unroll
            for (int j2 = 0; j2 < 2; j2++) {
                uint32_t r4[4];
                ldmBT(r4, sB + offB(ks * 16 + bRow, (w & 3) * 4 + j2 * 2 + bSel));
                bf[2 * j2][0] = r4[0]; bf[2 * j2][1] = r4[1];
                bf[2 * j2 + 1][0] = r4[2]; bf[2 * j2 + 1][1] = r4[3];
            }
#pragma unroll
            for (int i = 0; i < 4; i++)
#pragma unroll
                for (int j = 0; j < 4; j++)
                    mma16(acc[i][j], af[i], bf[j]);
        }
    }

    // ---- epilogue ----
#pragma unroll
    for (int i = 0; i < 4; i++) {
        const int r0 = rowBase + wm + i * 16 + gid;
#pragma unroll
        for (int j = 0; j < 4; j++) {
            const int cn = colBase + wn + j * 8 + 2 * tg;
            float v0 = acc[i][j][0], v1 = acc[i][j][1];
            float v2 = acc[i][j][2], v3 = acc[i][j][3];
            if (isKan) {
                __half* C = comb + 1024;
                *(__half2*)(C + (size_t)r0 * NCOMB + cn) = __floats2half2_rn(v0, v1);
                *(__half2*)(C + (size_t)(r0 + 8) * NCOMB + cn) = __floats2half2_rn(v2, v3);
            } else {
                float2 p0; p0.x = v0; p0.y = v1;
                float2 p1; p1.x = v2; p1.y = v3;
                *(float2*)(z + (size_t)r0 * 4096 + cn) = p0;
                *(float2*)(z + (size_t)(r0 + 8) * 4096 + cn) = p1;
            }
        }
    }
}

// =====================================================================
// Combine GEMM, split-K x2 via blockIdx.z -> fp32 partials.
// =====================================================================
__global__ __launch_bounds__(256, 2) void gemm_comb(
    const __half* __restrict__ Ain, const __half* __restrict__ Bin,
    float* __restrict__ part)
{
    const int kz = blockIdx.z;           // 0/1 -> K halves
    const __half* A = Ain + kz * 2048;                   // col offset in [2048,4096]
    const __half* B = Bin + (size_t)kz * 2048 * 1024;    // row offset in [4096,1024]
    float* C = part + (size_t)kz * BDIM * 1024;
    const int lda = NCOMB, ldb = 1024, K = 2048;

    const int tid = threadIdx.x;
    const int lane = tid & 31;
    const int w = tid >> 5;
    const int rowBase = blockIdx.y * 128;
    const int colBase = blockIdx.x * 128;
    const uint32_t sb = smem_u32(smem_h);

    float acc[4][4][4];
#pragma unroll
    for (int i = 0; i < 4; i++)
#pragma unroll
        for (int j = 0; j < 4; j++)
#pragma unroll
            for (int q = 0; q < 4; q++) acc[i][j][q] = 0.0f;

    const int nk = K / BKH;

    auto load_stage = [&](int t, int s) {
        const int kBase = t * BKH;
        const uint32_t sA = sb + s * HSTG;
        const uint32_t sB = sA + HAB;
#pragma unroll
        for (int i = 0; i < 4; i++) {
            int idx = i * 256 + tid;
            int r = idx >> 3, c = idx & 7;
            cp16(sA + offA(r, c), A + (size_t)(rowBase + r) * lda + kBase + c * 8);
        }
#pragma unroll
        for (int i = 0; i < 4; i++) {
            int idx = i * 256 + tid;
            int r = idx >> 4, c = idx & 15;
            cp16(sB + offB(r, c), B + (size_t)(kBase + r) * ldb + colBase + c * 8);
        }
    };

#pragma unroll
    for (int s = 0; s < HSSTG - 1; s++) { load_stage(s, s); cp_commit(); }

    const int wm = (w >> 2) * 64;
    const int wn = (w & 3) * 32;
    const int gid = lane >> 2;
    const int tg  = lane & 3;
    const int aRow = lane & 15;
    const int aSel = lane >> 4;
    const int bRow = lane & 15;
    const int bSel = lane >> 4;

    for (int t = 0; t < nk; t++) {
        cp_wait<HSSTG - 2>();
        __syncthreads();
        const int tn = t + HSSTG - 1;
        if (tn < nk) load_stage(tn, tn % HSSTG);
        cp_commit();

        const uint32_t sA = sb + (t % HSSTG) * HSTG;
        const uint32_t sB = sA + HAB;

#pragma unroll
        for (int ks = 0; ks < 4; ks++) {
            uint32_t af[4][4], bf[4][2];
#pragma unroll
            for (int i = 0; i < 4; i++)
                ldmA(af[i], sA + offA(wm + i * 16 + aRow, 2 * ks + aSel));
#pragma unroll
            for (int j2 = 0; j2 < 2; j2++) {
                uint32_t r4[4];
                ldmBT(r4, sB + offB(ks * 16 + bRow, (w & 3) * 4 + j2 * 2 + bSel));
                bf[2 * j2][0] = r4[0]; bf[2 * j2][1] = r4[1];
                bf[2 * j2 + 1][0] = r4[2]; bf[2 * j2 + 1][1] = r4[3];
            }
#pragma unroll
            for (int i = 0; i < 4; i++)
#pragma unroll
                for (int j = 0; j < 4; j++)
                    mma16(acc[i][j], af[i], bf[j]);
        }
    }

#pragma unroll
    for (int i = 0; i < 4; i++) {
        const int r0 = rowBase + wm + i * 16 + gid;
#pragma unroll
        for (int j = 0; j < 4; j++) {
            const int cn = colBase + wn + j * 8 + 2 * tg;
            float2 p0; p0.x = acc[i][j][0]; p0.y = acc[i][j][1];
            float2 p1; p1.x = acc[i][j][2]; p1.y = acc[i][j][3];
            *(float2*)(C + (size_t)r0 * 1024 + cn) = p0;
            *(float2*)(C + (size_t)(r0 + 8) * 1024 + cn) = p1;
        }
    }
}

// out = p0 + p1 + bias
__global__ void add_bias_kernel(const float* __restrict__ part,
                                const float* __restrict__ bias,
                                float* __restrict__ out)
{
    int i = blockIdx.x * 256 + threadIdx.x;      // per 4 elems
    long e = (long)i * 4;
    int u = (int)(e & 1023);
    float4 a = *(const float4*)(part + e);
    float4 b = *(const float4*)(part + (size_t)BDIM * 1024 + e);
    float4 bs = *(const float4*)(bias + u);
    float4 o;
    o.x = a.x + b.x + bs.x;
    o.y = a.y + b.y + bs.y;
    o.z = a.z + b.z + bs.z;
    o.w = a.w + b.w + bs.w;
    *(float4*)(out + e) = o;
}

// =====================================================================
// Weight conversion (16 elems/thread)
// =====================================================================
__device__ __forceinline__ void cvt8(const float* s, __half* d) {
    float4 v0 = *(const float4*)s;
    float4 v1 = *(const float4*)(s + 4);
    __half2 h[4];
    h[0] = __floats2half2_rn(v0.x, v0.y);
    h[1] = __floats2half2_rn(v0.z, v0.w);
    h[2] = __floats2half2_rn(v1.x, v1.y);
    h[3] = __floats2half2_rn(v1.z, v1.w);
    *(uint4*)d = *(uint4*)h;
}

__global__ void cvt_lstm(const float* __restrict__ wk, const float* __restrict__ wr,
                         __half* __restrict__ o)
{
    long e = ((long)blockIdx.x * 256 + threadIdx.x) * 16;
    int r = (int)(e >> 12), n = (int)(e & 4095);
    const float* s = (r < 1024) ? wk + (size_t)r * 4096 + n
                                : wr + (size_t)(r - 1024) * 4096 + n;
    cvt8(s, o + e);
    cvt8(s + 8, o + e + 8);
}

__global__ void cvt_kan(const float* __restrict__ bw, const float* __restrict__ sw,
                        __half* __restrict__ o)
{
    int col = (blockIdx.x * 128 + threadIdx.x) * 8;   // grid.x = 3
    int l = col >> 10, u = col & 1023;
#pragma unroll
    for (int h = 0; h < 2; h++) {
        int k = blockIdx.y + h * 4608;
        const float* s = (k < 1024)
            ? bw + ((size_t)l * 1024 + k) * 1024 + u
            : sw + ((size_t)l * 8192 + (k - 1024)) * 1024 + u;
        cvt8(s, o + (size_t)k * 3072 + col);
    }
}

__global__ void cvt_comb(const float* __restrict__ wc, __half* __restrict__ o)
{
    long e = ((long)blockIdx.x * 256 + threadIdx.x) * 16;
    cvt8(wc + e, o + e);
    cvt8(wc + e + 8, o + e + 8);
}

// =====================================================================
// Elementwise producers
// =====================================================================
__global__ void concat_xh_kernel(const float* __restrict__ x,
                                 const float* __restrict__ h,
                                 __half* __restrict__ xh)
{
    long e = ((long)blockIdx.x * 256 + threadIdx.x) * 16;
    int b = (int)(e >> 11), c = (int)(e & 2047);
    const float* src = (c < 1024) ? x + (size_t)b * 1024 + c
                                  : h + (size_t)b * 1024 + (c - 1024);
    cvt8(src, xh + e);
    cvt8(src + 8, xh + e + 8);
}

__global__ void lstm_gates_kernel(const float* __restrict__ z,
                                  const float* __restrict__ bias,
                                  const float* __restrict__ c_prev,
                                  float* __restrict__ out_h,
                                  float* __restrict__ out_c,
                                  __half* __restrict__ comb)
{
    int i = blockIdx.x * 256 + threadIdx.x;      // per 4 u
    int b = i >> 8, u = (i & 255) * 4;
    const float* zr = z + (size_t)b * 4096;
    float4 zi = *(const float4*)(zr + u);
    float4 zf = *(const float4*)(zr + 1024 + u);
    float4 zg = *(const float4*)(zr + 2048 + u);
    float4 zo = *(const float4*)(zr + 3072 + u);
    float4 bi = *(const float4*)(bias + u);
    float4 bf = *(const float4*)(bias + 1024 + u);
    float4 bg = *(const float4*)(bias + 2048 + u);
    float4 bo = *(const float4*)(bias + 3072 + u);
    float4 cp = *(const float4*)(c_prev + (size_t)b * 1024 + u);

    float hh[4], cc[4];
#pragma unroll
    for (int q = 0; q < 4; q++) {
        float vi = (&zi.x)[q] + (&bi.x)[q];
        float vf = (&zf.x)[q] + (&bf.x)[q];
        float vg = (&zg.x)[q] + (&bg.x)[q];
        float vo = (&zo.x)[q] + (&bo.x)[q];
        float si = 1.0f / (1.0f + expf(-vi));
        float sf = 1.0f / (1.0f + expf(-vf));
        float so = 1.0f / (1.0f + expf(-vo));
        float c = sf * (&cp.x)[q] + si * tanhf(vg);
        hh[q] = so * tanhf(c);
        cc[q] = c;
    }
    float4 ho; ho.x = hh[0]; ho.y = hh[1]; ho.z = hh[2]; ho.w = hh[3];
    float4 co; co.x = cc[0]; co.y = cc[1]; co.z = cc[2]; co.w = cc[3];
    *(float4*)(out_h + (size_t)b * 1024 + u) = ho;
    *(float4*)(out_c + (size_t)b * 1024 + u) = co;
    __half2 hc[2];
    hc[0] = __floats2half2_rn(hh[0], hh[1]);
    hc[1] = __floats2half2_rn(hh[2], hh[3]);
    *(uint2*)(comb + (size_t)b * NCOMB + u) = *(uint2*)hc;
}

__device__ __forceinline__ float knot(int j) {
    return -1.0f + 0.4f * (float)(j - 3);
}
__global__ void act_kernel(const float* __restrict__ x, __half* __restrict__ act)
{
    int i = blockIdx.x * blockDim.x + threadIdx.x;
    if (i >= BDIM * DDIM) return;
    int b = i / DDIM, d = i - b * DDIM;
    float xv = x[i];
    float s = xv / (1.0f + expf(-xv));

    float bb[11];
#pragma unroll
    for (int j = 0; j < 11; j++)
        bb[j] = (xv >= knot(j) && xv < knot(j + 1)) ? 1.0f : 0.0f;
#pragma unroll
    for (int p = 1; p <= 3; p++) {
        const float invp = 2.5f / (float)p;     // 1/(0.4*p)
#pragma unroll
        for (int j = 0; j <= 10 - p; j++) {
            bb[j] = (xv - knot(j)) * invp * bb[j]
                  + (knot(j + p + 1) - xv) * invp * bb[j + 1];
        }
    }
    __half* row = act + (size_t)b * KACT;
    row[d] = __float2half(s);
    __half2 o[4];
    o[0] = __floats2half2_rn(bb[0], bb[1]);
    o[1] = __floats2half2_rn(bb[2], bb[3]);
    o[2] = __floats2half2_rn(bb[4], bb[5]);
    o[3] = __floats2half2_rn(bb[6], bb[7]);
    *(uint4*)(row + DDIM + d * NB) = *(uint4*)o;
}

// =====================================================================
// Launch
// =====================================================================
extern "C" void kernel_launch(void* const* d_in, const int* in_sizes, int n_in,
                              void* d_out, int out_size)
{
    const float* x       = (const float*)d_in[0];
    const float* h_prev  = (const float*)d_in[1];
    const float* c_prev  = (const float*)d_in[2];
    const float* lstm_k  = (const float*)d_in[3];
    const float* lstm_rk = (const float*)d_in[4];
    const float* lstm_b  = (const float*)d_in[5];
    const float* kan_bw  = (const float*)d_in[6];
    const float* kan_sw  = (const float*)d_in[7];
    const float* comb_w  = (const float*)d_in[8];
    const float* comb_b  = (const float*)d_in[9];

    float* out   = (float*)d_out;
    float* out_h = out + (size_t)BDIM * UDIM;
    float* out_c = out + (size_t)2 * BDIM * UDIM;

    __half *xh, *act, *comb, *wl, *wk, *wc;
    float* z;
    cudaGetSymbolAddress((void**)&xh,   g_xh);
    cudaGetSymbolAddress((void**)&z,    g_z);
    cudaGetSymbolAddress((void**)&act,  g_act);
    cudaGetSymbolAddress((void**)&comb, g_comb);
    cudaGetSymbolAddress((void**)&wl,   g_wl);
    cudaGetSymbolAddress((void**)&wk,   g_wk);
    cudaGetSymbolAddress((void**)&wc,   g_wc);

    const int DYN = HSSTG * HSTG;   // 98304
    cudaFuncSetAttribute(gemm_fused, cudaFuncAttributeMaxDynamicSharedMemorySize, DYN);
    cudaFuncSetAttribute(gemm_comb,  cudaFuncAttributeMaxDynamicSharedMemorySize, DYN);

    // Weight conversion / fusion
    cvt_lstm<<<2048 * 4096 / 16 / 256, 256>>>(lstm_k, lstm_rk, wl);
    cvt_kan<<<dim3(3, 4608), 128>>>(kan_bw, kan_sw, wk);
    cvt_comb<<<4096 * 1024 / 16 / 256, 256>>>(comb_w, wc);

    // Activation producers
    concat_xh_kernel<<<BDIM * 2048 / 16 / 256, 256>>>(x, h_prev, xh);
    act_kernel<<<(BDIM * DDIM + 255) / 256, 256>>>(x, act);

    // Fused LSTM + KAN GEMMs (896 CTAs; KAN first)
    gemm_fused<<<896, 256, DYN>>>(act, wk, xh, wl, comb, z);

    // Gates (z -> h, c, comb[:,0:1024])
    lstm_gates_kernel<<<BDIM * UDIM / 4 / 256, 256>>>(
        z, lstm_b, c_prev, out_h, out_c, comb);

    // Combine split-K x2 -> partials in g_z (z is dead now)
    gemm_comb<<<dim3(1024 / 128, BDIM / 128, 2), 256, DYN>>>(comb, wc, z);

    // out = p0 + p1 + bias
    add_bias_kernel<<<BDIM * 1024 / 4 / 256, 256>>>(z, comb_b, out);
}

// round 9
// speedup vs baseline: 1.6098x; 1.1078x over previous
#include <cuda_runtime.h>
#include <cuda_fp16.h>
#include <cstdint>
#include <math.h>

// ---- Problem constants ----
#define BDIM 2048
#define DDIM 1024
#define UDIM 1024
#define NB   8
#define KACT 9216
#define NCOMB 4096

// ---- Scratch (device globals; no allocation allowed) ----
__device__ __half g_xh[BDIM * 2048];               // [x | h_prev] fp16
__device__ float  g_z[BDIM * 4096];                // LSTM preacts; later mega partials
__device__ __half g_act[(size_t)BDIM * KACT];      // [silu | bases] fp16
__device__ __half g_h16[BDIM * 1024];              // h fp16
__device__ __half g_wl[(size_t)2048 * 4096];       // fused [Wk;Wr]
__device__ __half g_wk[(size_t)KACT * 3072];       // fused KAN weights [9216 x 3072]
__device__ __half g_wc[(size_t)4096 * 1024];       // combine weights fp16
__device__ __half g_wt[(size_t)KACT * 1024];       // W-tilde = wk @ wc[1024:4096]  [9216 x 1024]

// ---- PTX helpers ----
__device__ __forceinline__ uint32_t smem_u32(const void* p) {
    uint32_t a;
    asm("{ .reg .u64 t; cvta.to.shared.u64 t, %1; cvt.u32.u64 %0, t; }"
        : "=r"(a) : "l"(p));
    return a;
}
__device__ __forceinline__ void cp16(uint32_t s, const void* g) {
    asm volatile("cp.async.cg.shared.global [%0], [%1], 16;" :: "r"(s), "l"(g));
}
__device__ __forceinline__ void cp_commit() {
    asm volatile("cp.async.commit_group;" ::: "memory");
}
template<int N> __device__ __forceinline__ void cp_wait() {
    asm volatile("cp.async.wait_group %0;" :: "n"(N) : "memory");
}
__device__ __forceinline__ void ldmA(uint32_t* r, uint32_t a) {
    asm volatile("ldmatrix.sync.aligned.m8n8.x4.shared.b16 {%0,%1,%2,%3}, [%4];"
                 : "=r"(r[0]), "=r"(r[1]), "=r"(r[2]), "=r"(r[3]) : "r"(a));
}
__device__ __forceinline__ void ldmBT(uint32_t* r, uint32_t a) {
    asm volatile("ldmatrix.sync.aligned.m8n8.x4.trans.shared.b16 {%0,%1,%2,%3}, [%4];"
                 : "=r"(r[0]), "=r"(r[1]), "=r"(r[2]), "=r"(r[3]) : "r"(a));
}
__device__ __forceinline__ void mma16(float* c, const uint32_t* a, const uint32_t* b) {
    asm volatile(
        "mma.sync.aligned.m16n8k16.row.col.f32.f16.f16.f32 "
        "{%0,%1,%2,%3}, {%4,%5,%6,%7}, {%8,%9}, {%0,%1,%2,%3};"
        : "+f"(c[0]), "+f"(c[1]), "+f"(c[2]), "+f"(c[3])
        : "r"(a[0]), "r"(a[1]), "r"(a[2]), "r"(a[3]), "r"(b[0]), "r"(b[1]));
}

#define BKH 64
#define HAB 16384
#define HSTG 32768
#define HSSTG 3

extern __shared__ char smem_h[];

__device__ __forceinline__ uint32_t offA(int r, int c) {
    return (uint32_t)(r * 128 + ((c ^ (r & 7)) << 4));
}
__device__ __forceinline__ uint32_t offB(int k, int c) {
    return (uint32_t)(k * 256 + ((c ^ (k & 7)) << 4));
}

// =====================================================================
// Fused W-tilde + LSTM GEMM launch. 1088 CTAs:
//   bid <  576 : W~  tile (A=wk [9216,3072], B=wc+1024*1024, K=3072, fp16 -> g_wt)
//   bid >= 576 : LSTM tile (A=xh  K=2048, B=wl ldb=4096, fp32 -> z)
// =====================================================================
__global__ __launch_bounds__(256, 2) void gemm_fused(
    const __half* __restrict__ wkp, const __half* __restrict__ wcp,
    const __half* __restrict__ xhp, const __half* __restrict__ wlp,
    __half* __restrict__ wt, float* __restrict__ z)
{
    const int bid = blockIdx.x;
    const bool isWt = bid < 576;
    const __half *A, *B;
    int lda, ldb, K, rowBase, colBase;
    if (isWt) {
        A = wkp; B = wcp + (size_t)1024 * 1024; lda = 3072; ldb = 1024; K = 3072;
        colBase = (bid & 7) * 128; rowBase = (bid >> 3) * 128;
    } else {
        int b2 = bid - 576;
        A = xhp; B = wlp; lda = 2048; ldb = 4096; K = 2048;
        colBase = (b2 & 31) * 128; rowBase = (b2 >> 5) * 128;
    }

    const int tid = threadIdx.x;
    const int lane = tid & 31;
    const int w = tid >> 5;
    const uint32_t sb = smem_u32(smem_h);

    float acc[4][4][4];
#pragma unroll
    for (int i = 0; i < 4; i++)
#pragma unroll
        for (int j = 0; j < 4; j++)
#pragma unroll
            for (int q = 0; q < 4; q++) acc[i][j][q] = 0.0f;

    const int nk = K / BKH;

    auto load_stage = [&](int t, int s) {
        const int kBase = t * BKH;
        const uint32_t sA = sb + s * HSTG;
        const uint32_t sB = sA + HAB;
#pragma unroll
        for (int i = 0; i < 4; i++) {
            int idx = i * 256 + tid;
            int r = idx >> 3, c = idx & 7;
            cp16(sA + offA(r, c), A + (size_t)(rowBase + r) * lda + kBase + c * 8);
        }
#pragma unroll
        for (int i = 0; i < 4; i++) {
            int idx = i * 256 + tid;
            int r = idx >> 4, c = idx & 15;
            cp16(sB + offB(r, c), B + (size_t)(kBase + r) * ldb + colBase + c * 8);
        }
    };

#pragma unroll
    for (int s = 0; s < HSSTG - 1; s++) { load_stage(s, s); cp_commit(); }

    const int wm = (w >> 2) * 64;
    const int wn = (w & 3) * 32;
    const int gid = lane >> 2;
    const int tg  = lane & 3;
    const int aRow = lane & 15;
    const int aSel = lane >> 4;
    const int bRow = lane & 15;
    const int bSel = lane >> 4;

    for (int t = 0; t < nk; t++) {
        cp_wait<HSSTG - 2>();
        __syncthreads();
        const int tn = t + HSSTG - 1;
        if (tn < nk) load_stage(tn, tn % HSSTG);
        cp_commit();

        const uint32_t sA = sb + (t % HSSTG) * HSTG;
        const uint32_t sB = sA + HAB;

#pragma unroll
        for (int ks = 0; ks < 4; ks++) {
            uint32_t af[4][4], bf[4][2];
#pragma unroll
            for (int i = 0; i < 4; i++)
                ldmA(af[i], sA + offA(wm + i * 16 + aRow, 2 * ks + aSel));
#pragma unroll
            for (int j2 = 0; j2 < 2; j2++) {
                uint32_t r4[4];
                ldmBT(r4, sB + offB(ks * 16 + bRow, (w & 3) * 4 + j2 * 2 + bSel));
                bf[2 * j2][0] = r4[0]; bf[2 * j2][1] = r4[1];
                bf[2 * j2 + 1][0] = r4[2]; bf[2 * j2 + 1][1] = r4[3];
            }
#pragma unroll
            for (int i = 0; i < 4; i++)
#pragma unroll
                for (int j = 0; j < 4; j++)
                    mma16(acc[i][j], af[i], bf[j]);
        }
    }

    // ---- epilogue ----
#pragma unroll
    for (int i = 0; i < 4; i++) {
        const int r0 = rowBase + wm + i * 16 + gid;
#pragma unroll
        for (int j = 0; j < 4; j++) {
            const int cn = colBase + wn + j * 8 + 2 * tg;
            float v0 = acc[i][j][0], v1 = acc[i][j][1];
            float v2 = acc[i][j][2], v3 = acc[i][j][3];
            if (isWt) {
                *(__half2*)(wt + (size_t)r0 * 1024 + cn) = __floats2half2_rn(v0, v1);
                *(__half2*)(wt + (size_t)(r0 + 8) * 1024 + cn) = __floats2half2_rn(v2, v3);
            } else {
                float2 p0; p0.x = v0; p0.y = v1;
                float2 p1; p1.x = v2; p1.y = v3;
                *(float2*)(z + (size_t)r0 * 4096 + cn) = p0;
                *(float2*)(z + (size_t)(r0 + 8) * 4096 + cn) = p1;
            }
        }
    }
}

// =====================================================================
// Mega combine GEMM: [h | silu | bases] @ [Wc_lstm ; W~] -> partials.
// Split-K x2 (blockIdx.z). Split pointers handle the concatenations:
//   kz=0: k 0..5119  : A: k<1024 -> h16, else act[k-1024]; B: k<1024 -> wc, else wt[k-1024]
//   kz=1: k 5120..10239: A = act+4096; B = wt+4096*1024
// =====================================================================
__global__ __launch_bounds__(256, 2) void gemm_mega(
    const __half* __restrict__ h16, const __half* __restrict__ actp,
    const __half* __restrict__ wcp, const __half* __restrict__ wtp,
    float* __restrict__ part)
{
    const int kz = blockIdx.z;
    const __half *A0, *A1, *B0, *B1;
    int lda0, lda1, ksA;
    if (kz == 0) {
        A0 = h16; lda0 = 1024; A1 = actp; lda1 = KACT; ksA = 1024;
        B0 = wcp; B1 = wtp;
    } else {
        A0 = nullptr; lda0 = 0; A1 = actp + 4096; lda1 = KACT; ksA = 0;
        B0 = nullptr; B1 = wtp + (size_t)4096 * 1024;
    }
    float* C = part + (size_t)kz * BDIM * 1024;
    const int K = 5120;

    const int tid = threadIdx.x;
    const int lane = tid & 31;
    const int w = tid >> 5;
    const int rowBase = blockIdx.y * 128;
    const int colBase = blockIdx.x * 128;
    const uint32_t sb = smem_u32(smem_h);

    float acc[4][4][4];
#pragma unroll
    for (int i = 0; i < 4; i++)
#pragma unroll
        for (int j = 0; j < 4; j++)
#pragma unroll
            for (int q = 0; q < 4; q++) acc[i][j][q] = 0.0f;

    const int nk = K / BKH;

    auto load_stage = [&](int t, int s) {
        const int kBase = t * BKH;      // tile fully on one side (ksA % 64 == 0)
        const uint32_t sA = sb + s * HSTG;
        const uint32_t sB = sA + HAB;
        const bool lo = kBase < ksA;
        const __half* Ap = lo ? A0 : A1 + (kBase - ksA);
        const int lda = lo ? lda0 : lda1;
        const int ka = lo ? kBase : 0;
        const __half* Bp = lo ? B0 + (size_t)kBase * 1024
                              : B1 + (size_t)(kBase - ksA) * 1024;
#pragma unroll
        for (int i = 0; i < 4; i++) {
            int idx = i * 256 + tid;
            int r = idx >> 3, c = idx & 7;
            cp16(sA + offA(r, c), Ap + (size_t)(rowBase + r) * lda + ka + c * 8);
        }
#pragma unroll
        for (int i = 0; i < 4; i++) {
            int idx = i * 256 + tid;
            int r = idx >> 4, c = idx & 15;
            cp16(sB + offB(r, c), Bp + (size_t)r * 1024 + colBase + c * 8);
        }
    };

#pragma unroll
    for (int s = 0; s < HSSTG - 1; s++) { load_stage(s, s); cp_commit(); }

    const int wm = (w >> 2) * 64;
    const int wn = (w & 3) * 32;
    const int gid = lane >> 2;
    const int tg  = lane & 3;
    const int aRow = lane & 15;
    const int aSel = lane >> 4;
    const int bRow = lane & 15;
    const int bSel = lane >> 4;

    for (int t = 0; t < nk; t++) {
        cp_wait<HSSTG - 2>();
        __syncthreads();
        const int tn = t + HSSTG - 1;
        if (tn < nk) load_stage(tn, tn % HSSTG);
        cp_commit();

        const uint32_t sA = sb + (t % HSSTG) * HSTG;
        const uint32_t sB = sA + HAB;

#pragma unroll
        for (int ks = 0; ks < 4; ks++) {
            uint32_t af[4][4], bf[4][2];
#pragma unroll
            for (int i = 0; i < 4; i++)
                ldmA(af[i], sA + offA(wm + i * 16 + aRow, 2 * ks + aSel));
#pragma unroll
            for (int j2 = 0; j2 < 2; j2++) {
                uint32_t r4[4];
                ldmBT(r4, sB + offB(ks * 16 + bRow, (w & 3) * 4 + j2 * 2 + bSel));
                bf[2 * j2][0] = r4[0]; bf[2 * j2][1] = r4[1];
                bf[2 * j2 + 1][0] = r4[2]; bf[2 * j2 + 1][1] = r4[3];
            }
#pragma unroll
            for (int i = 0; i < 4; i++)
#pragma unroll
                for (int j = 0; j < 4; j++)
                    mma16(acc[i][j], af[i], bf[j]);
        }
    }

#pragma unroll
    for (int i = 0; i < 4; i++) {
        const int r0 = rowBase + wm + i * 16 + gid;
#pragma unroll
        for (int j = 0; j < 4; j++) {
            const int cn = colBase + wn + j * 8 + 2 * tg;
            float2 p0; p0.x = acc[i][j][0]; p0.y = acc[i][j][1];
            float2 p1; p1.x = acc[i][j][2]; p1.y = acc[i][j][3];
            *(float2*)(C + (size_t)r0 * 1024 + cn) = p0;
            *(float2*)(C + (size_t)(r0 + 8) * 1024 + cn) = p1;
        }
    }
}

// out = p0 + p1 + bias
__global__ void add_bias_kernel(const float* __restrict__ part,
                                const float* __restrict__ bias,
                                float* __restrict__ out)
{
    int i = blockIdx.x * 256 + threadIdx.x;
    long e = (long)i * 4;
    int u = (int)(e & 1023);
    float4 a = *(const float4*)(part + e);
    float4 b = *(const float4*)(part + (size_t)BDIM * 1024 + e);
    float4 bs = *(const float4*)(bias + u);
    float4 o;
    o.x = a.x + b.x + bs.x;
    o.y = a.y + b.y + bs.y;
    o.z = a.z + b.z + bs.z;
    o.w = a.w + b.w + bs.w;
    *(float4*)(out + e) = o;
}

// =====================================================================
// Weight conversion
// =====================================================================
__device__ __forceinline__ void cvt8(const float* s, __half* d) {
    float4 v0 = *(const float4*)s;
    float4 v1 = *(const float4*)(s + 4);
    __half2 h[4];
    h[0] = __floats2half2_rn(v0.x, v0.y);
    h[1] = __floats2half2_rn(v0.z, v0.w);
    h[2] = __floats2half2_rn(v1.x, v1.y);
    h[3] = __floats2half2_rn(v1.z, v1.w);
    *(uint4*)d = *(uint4*)h;
}

__global__ void cvt_lstm(const float* __restrict__ wk, const float* __restrict__ wr,
                         __half* __restrict__ o)
{
    long e = ((long)blockIdx.x * 256 + threadIdx.x) * 16;
    int r = (int)(e >> 12), n = (int)(e & 4095);
    const float* s = (r < 1024) ? wk + (size_t)r * 4096 + n
                                : wr + (size_t)(r - 1024) * 4096 + n;
    cvt8(s, o + e);
    cvt8(s + 8, o + e + 8);
}

__global__ void cvt_kan(const float* __restrict__ bw, const float* __restrict__ sw,
                        __half* __restrict__ o)
{
    int col = (blockIdx.x * 128 + threadIdx.x) * 8;   // grid.x = 3
    int l = col >> 10, u = col & 1023;
#pragma unroll
    for (int h = 0; h < 2; h++) {
        int k = blockIdx.y + h * 4608;
        const float* s = (k < 1024)
            ? bw + ((size_t)l * 1024 + k) * 1024 + u
            : sw + ((size_t)l * 8192 + (k - 1024)) * 1024 + u;
        cvt8(s, o + (size_t)k * 3072 + col);
    }
}

__global__ void cvt_comb(const float* __restrict__ wc, __half* __restrict__ o)
{
    long e = ((long)blockIdx.x * 256 + threadIdx.x) * 16;
    cvt8(wc + e, o + e);
    cvt8(wc + e + 8, o + e + 8);
}

// =====================================================================
// Elementwise producers
// =====================================================================
__global__ void concat_xh_kernel(const float* __restrict__ x,
                                 const float* __restrict__ h,
                                 __half* __restrict__ xh)
{
    long e = ((long)blockIdx.x * 256 + threadIdx.x) * 16;
    int b = (int)(e >> 11), c = (int)(e & 2047);
    const float* src = (c < 1024) ? x + (size_t)b * 1024 + c
                                  : h + (size_t)b * 1024 + (c - 1024);
    cvt8(src, xh + e);
    cvt8(src + 8, xh + e + 8);
}

__global__ void lstm_gates_kernel(const float* __restrict__ z,
                                  const float* __restrict__ bias,
                                  const float* __restrict__ c_prev,
                                  float* __restrict__ out_h,
                                  float* __restrict__ out_c,
                                  __half* __restrict__ h16)
{
    int i = blockIdx.x * 256 + threadIdx.x;      // per 4 u
    int b = i >> 8, u = (i & 255) * 4;
    const float* zr = z + (size_t)b * 4096;
    float4 zi = *(const float4*)(zr + u);
    float4 zf = *(const float4*)(zr + 1024 + u);
    float4 zg = *(const float4*)(zr + 2048 + u);
    float4 zo = *(const float4*)(zr + 3072 + u);
    float4 bi = *(const float4*)(bias + u);
    float4 bf = *(const float4*)(bias + 1024 + u);
    float4 bg = *(const float4*)(bias + 2048 + u);
    float4 bo = *(const float4*)(bias + 3072 + u);
    float4 cp = *(const float4*)(c_prev + (size_t)b * 1024 + u);

    float hh[4], cc[4];
#pragma unroll
    for (int q = 0; q < 4; q++) {
        float vi = (&zi.x)[q] + (&bi.x)[q];
        float vf = (&zf.x)[q] + (&bf.x)[q];
        float vg = (&zg.x)[q] + (&bg.x)[q];
        float vo = (&zo.x)[q] + (&bo.x)[q];
        float si = 1.0f / (1.0f + expf(-vi));
        float sf = 1.0f / (1.0f + expf(-vf));
        float so = 1.0f / (1.0f + expf(-vo));
        float c = sf * (&cp.x)[q] + si * tanhf(vg);
        hh[q] = so * tanhf(c);
        cc[q] = c;
    }
    float4 ho; ho.x = hh[0]; ho.y = hh[1]; ho.z = hh[2]; ho.w = hh[3];
    float4 co; co.x = cc[0]; co.y = cc[1]; co.z = cc[2]; co.w = cc[3];
    *(float4*)(out_h + (size_t)b * 1024 + u) = ho;
    *(float4*)(out_c + (size_t)b * 1024 + u) = co;
    __half2 hc[2];
    hc[0] = __floats2half2_rn(hh[0], hh[1]);
    hc[1] = __floats2half2_rn(hh[2], hh[3]);
    *(uint2*)(h16 + (size_t)b * 1024 + u) = *(uint2*)hc;
}

__device__ __forceinline__ float knot(int j) {
    return -1.0f + 0.4f * (float)(j - 3);
}
__global__ void act_kernel(const float* __restrict__ x, __half* __restrict__ act)
{
    int i = blockIdx.x * blockDim.x + threadIdx.x;
    if (i >= BDIM * DDIM) return;
    int b = i / DDIM, d = i - b * DDIM;
    float xv = x[i];
    float s = xv / (1.0f + expf(-xv));

    float bb[11];
#pragma unroll
    for (int j = 0; j < 11; j++)
        bb[j] = (xv >= knot(j) && xv < knot(j + 1)) ? 1.0f : 0.0f;
#pragma unroll
    for (int p = 1; p <= 3; p++) {
        const float invp = 2.5f / (float)p;
#pragma unroll
        for (int j = 0; j <= 10 - p; j++) {
            bb[j] = (xv - knot(j)) * invp * bb[j]
                  + (knot(j + p + 1) - xv) * invp * bb[j + 1];
        }
    }
    __half* row = act + (size_t)b * KACT;
    row[d] = __float2half(s);
    __half2 o[4];
    o[0] = __floats2half2_rn(bb[0], bb[1]);
    o[1] = __floats2half2_rn(bb[2], bb[3]);
    o[2] = __floats2half2_rn(bb[4], bb[5]);
    o[3] = __floats2half2_rn(bb[6], bb[7]);
    *(uint4*)(row + DDIM + d * NB) = *(uint4*)o;
}

// =====================================================================
// Launch
// =====================================================================
extern "C" void kernel_launch(void* const* d_in, const int* in_sizes, int n_in,
                              void* d_out, int out_size)
{
    const float* x       = (const float*)d_in[0];
    const float* h_prev  = (const float*)d_in[1];
    const float* c_prev  = (const float*)d_in[2];
    const float* lstm_k  = (const float*)d_in[3];
    const float* lstm_rk = (const float*)d_in[4];
    const float* lstm_b  = (const float*)d_in[5];
    const float* kan_bw  = (const float*)d_in[6];
    const float* kan_sw  = (const float*)d_in[7];
    const float* comb_w  = (const float*)d_in[8];
    const float* comb_b  = (const float*)d_in[9];

    float* out   = (float*)d_out;
    float* out_h = out + (size_t)BDIM * UDIM;
    float* out_c = out + (size_t)2 * BDIM * UDIM;

    __half *xh, *act, *h16, *wl, *wk, *wc, *wt;
    float* z;
    cudaGetSymbolAddress((void**)&xh,  g_xh);
    cudaGetSymbolAddress((void**)&z,   g_z);
    cudaGetSymbolAddress((void**)&act, g_act);
    cudaGetSymbolAddress((void**)&h16, g_h16);
    cudaGetSymbolAddress((void**)&wl,  g_wl);
    cudaGetSymbolAddress((void**)&wk,  g_wk);
    cudaGetSymbolAddress((void**)&wc,  g_wc);
    cudaGetSymbolAddress((void**)&wt,  g_wt);

    const int DYN = HSSTG * HSTG;   // 98304
    cudaFuncSetAttribute(gemm_fused, cudaFuncAttributeMaxDynamicSharedMemorySize, DYN);
    cudaFuncSetAttribute(gemm_mega,  cudaFuncAttributeMaxDynamicSharedMemorySize, DYN);

    // Weight conversion / fusion
    cvt_lstm<<<2048 * 4096 / 16 / 256, 256>>>(lstm_k, lstm_rk, wl);
    cvt_kan<<<dim3(3, 4608), 128>>>(kan_bw, kan_sw, wk);
    cvt_comb<<<4096 * 1024 / 16 / 256, 256>>>(comb_w, wc);

    // Activation producers
    concat_xh_kernel<<<BDIM * 2048 / 16 / 256, 256>>>(x, h_prev, xh);
    act_kernel<<<(BDIM * DDIM + 255) / 256, 256>>>(x, act);

    // Fused W~ + LSTM GEMMs (1088 CTAs; W~ first — longer K)
    gemm_fused<<<1088, 256, DYN>>>(wk, wc, xh, wl, wt, z);

    // Gates (z -> h, c; h fp16 -> g_h16)
    lstm_gates_kernel<<<BDIM * UDIM / 4 / 256, 256>>>(
        z, lstm_b, c_prev, out_h, out_c, h16);

    // Mega combine split-K x2 -> partials in g_z (z is dead now)
    gemm_mega<<<dim3(1024 / 128, BDIM / 128, 2), 256, DYN>>>(h16, act, wc, wt, z);

    // out = p0 + p1 + bias
    add_bias_kernel<<<BDIM * 1024 / 4 / 256, 256>>>(z, comb_b, out);
}

// round 10
// speedup vs baseline: 1.6497x; 1.0248x over previous
#include <cuda_runtime.h>
#include <cuda_fp16.h>
#include <cstdint>
#include <math.h>

// ---- Problem constants ----
#define BDIM 2048
#define DDIM 1024
#define UDIM 1024
#define NB   8
#define KACT 9216
#define NCOMB 4096

// ---- Scratch (device globals; no allocation allowed) ----
__device__ __half g_xh[BDIM * 2048];               // [x | h_prev] fp16
__device__ float  g_z[BDIM * 4096];                // LSTM preacts; later mega partials
__device__ __half g_act[(size_t)BDIM * KACT];      // [silu | bases] fp16
__device__ __half g_h16[BDIM * 1024];              // h fp16
__device__ __half g_wl[(size_t)2048 * 4096];       // fused [Wk;Wr]
__device__ __half g_wk[(size_t)KACT * 3072];       // fused KAN weights [9216 x 3072]
__device__ __half g_wc[(size_t)4096 * 1024];       // combine weights fp16
__device__ __half g_wt[(size_t)KACT * 1024];       // W~ = wk @ wc[1024:4096]  [9216 x 1024]

// ---- PTX helpers ----
__device__ __forceinline__ uint32_t smem_u32(const void* p) {
    uint32_t a;
    asm("{ .reg .u64 t; cvta.to.shared.u64 t, %1; cvt.u32.u64 %0, t; }"
        : "=r"(a) : "l"(p));
    return a;
}
__device__ __forceinline__ void cp16(uint32_t s, const void* g) {
    asm volatile("cp.async.cg.shared.global [%0], [%1], 16;" :: "r"(s), "l"(g));
}
__device__ __forceinline__ void cp_commit() {
    asm volatile("cp.async.commit_group;" ::: "memory");
}
template<int N> __device__ __forceinline__ void cp_wait() {
    asm volatile("cp.async.wait_group %0;" :: "n"(N) : "memory");
}
__device__ __forceinline__ void ldmA(uint32_t* r, uint32_t a) {
    asm volatile("ldmatrix.sync.aligned.m8n8.x4.shared.b16 {%0,%1,%2,%3}, [%4];"
                 : "=r"(r[0]), "=r"(r[1]), "=r"(r[2]), "=r"(r[3]) : "r"(a));
}
__device__ __forceinline__ void ldmBT(uint32_t* r, uint32_t a) {
    asm volatile("ldmatrix.sync.aligned.m8n8.x4.trans.shared.b16 {%0,%1,%2,%3}, [%4];"
                 : "=r"(r[0]), "=r"(r[1]), "=r"(r[2]), "=r"(r[3]) : "r"(a));
}
__device__ __forceinline__ void mma16(float* c, const uint32_t* a, const uint32_t* b) {
    asm volatile(
        "mma.sync.aligned.m16n8k16.row.col.f32.f16.f16.f32 "
        "{%0,%1,%2,%3}, {%4,%5,%6,%7}, {%8,%9}, {%0,%1,%2,%3};"
        : "+f"(c[0]), "+f"(c[1]), "+f"(c[2]), "+f"(c[3])
        : "r"(a[0]), "r"(a[1]), "r"(a[2]), "r"(a[3]), "r"(b[0]), "r"(b[1]));
}

#define BKH 64
#define HAB 16384
#define HSTG 32768
#define HSSTG 3

extern __shared__ char smem_h[];

__device__ __forceinline__ uint32_t offA(int r, int c) {
    return (uint32_t)(r * 128 + ((c ^ (r & 7)) << 4));
}
__device__ __forceinline__ uint32_t offB(int k, int c) {
    return (uint32_t)(k * 256 + ((c ^ (k & 7)) << 4));
}

// =====================================================================
// Fused W-tilde + LSTM GEMM launch. 1088 CTAs:
//   bid <  576 : W~  tile (A=wk [9216,3072], B=wc+1024*1024, K=3072, fp16 -> g_wt)
//   bid >= 576 : LSTM tile (A=xh  K=2048, B=wl ldb=4096, fp32 -> z)
// =====================================================================
__global__ __launch_bounds__(256, 2) void gemm_fused(
    const __half* __restrict__ wkp, const __half* __restrict__ wcp,
    const __half* __restrict__ xhp, const __half* __restrict__ wlp,
    __half* __restrict__ wt, float* __restrict__ z)
{
    const int bid = blockIdx.x;
    const bool isWt = bid < 576;
    const __half *A, *B;
    int lda, ldb, K, rowBase, colBase;
    if (isWt) {
        A = wkp; B = wcp + (size_t)1024 * 1024; lda = 3072; ldb = 1024; K = 3072;
        colBase = (bid & 7) * 128; rowBase = (bid >> 3) * 128;
    } else {
        int b2 = bid - 576;
        A = xhp; B = wlp; lda = 2048; ldb = 4096; K = 2048;
        colBase = (b2 & 31) * 128; rowBase = (b2 >> 5) * 128;
    }

    const int tid = threadIdx.x;
    const int lane = tid & 31;
    const int w = tid >> 5;
    const uint32_t sb = smem_u32(smem_h);

    float acc[4][4][4];
#pragma unroll
    for (int i = 0; i < 4; i++)
#pragma unroll
        for (int j = 0; j < 4; j++)
#pragma unroll
            for (int q = 0; q < 4; q++) acc[i][j][q] = 0.0f;

    const int nk = K / BKH;

    auto load_stage = [&](int t, int s) {
        const int kBase = t * BKH;
        const uint32_t sA = sb + s * HSTG;
        const uint32_t sB = sA + HAB;
#pragma unroll
        for (int i = 0; i < 4; i++) {
            int idx = i * 256 + tid;
            int r = idx >> 3, c = idx & 7;
            cp16(sA + offA(r, c), A + (size_t)(rowBase + r) * lda + kBase + c * 8);
        }
#pragma unroll
        for (int i = 0; i < 4; i++) {
            int idx = i * 256 + tid;
            int r = idx >> 4, c = idx & 15;
            cp16(sB + offB(r, c), B + (size_t)(kBase + r) * ldb + colBase + c * 8);
        }
    };

#pragma unroll
    for (int s = 0; s < HSSTG - 1; s++) { load_stage(s, s); cp_commit(); }

    const int wm = (w >> 2) * 64;
    const int wn = (w & 3) * 32;
    const int gid = lane >> 2;
    const int tg  = lane & 3;
    const int aRow = lane & 15;
    const int aSel = lane >> 4;
    const int bRow = lane & 15;
    const int bSel = lane >> 4;

    for (int t = 0; t < nk; t++) {
        cp_wait<HSSTG - 2>();
        __syncthreads();
        const int tn = t + HSSTG - 1;
        if (tn < nk) load_stage(tn, tn % HSSTG);
        cp_commit();

        const uint32_t sA = sb + (t % HSSTG) * HSTG;
        const uint32_t sB = sA + HAB;

#pragma unroll
        for (int ks = 0; ks < 4; ks++) {
            uint32_t af[4][4], bf[4][2];
#pragma unroll
            for (int i = 0; i < 4; i++)
                ldmA(af[i], sA + offA(wm + i * 16 + aRow, 2 * ks + aSel));
#pragma unroll
            for (int j2 = 0; j2 < 2; j2++) {
                uint32_t r4[4];
                ldmBT(r4, sB + offB(ks * 16 + bRow, (w & 3) * 4 + j2 * 2 + bSel));
                bf[2 * j2][0] = r4[0]; bf[2 * j2][1] = r4[1];
                bf[2 * j2 + 1][0] = r4[2]; bf[2 * j2 + 1][1] = r4[3];
            }
#pragma unroll
            for (int i = 0; i < 4; i++)
#pragma unroll
                for (int j = 0; j < 4; j++)
                    mma16(acc[i][j], af[i], bf[j]);
        }
    }

    // ---- epilogue ----
#pragma unroll
    for (int i = 0; i < 4; i++) {
        const int r0 = rowBase + wm + i * 16 + gid;
#pragma unroll
        for (int j = 0; j < 4; j++) {
            const int cn = colBase + wn + j * 8 + 2 * tg;
            float v0 = acc[i][j][0], v1 = acc[i][j][1];
            float v2 = acc[i][j][2], v3 = acc[i][j][3];
            if (isWt) {
                *(__half2*)(wt + (size_t)r0 * 1024 + cn) = __floats2half2_rn(v0, v1);
                *(__half2*)(wt + (size_t)(r0 + 8) * 1024 + cn) = __floats2half2_rn(v2, v3);
            } else {
                float2 p0; p0.x = v0; p0.y = v1;
                float2 p1; p1.x = v2; p1.y = v3;
                *(float2*)(z + (size_t)r0 * 4096 + cn) = p0;
                *(float2*)(z + (size_t)(r0 + 8) * 4096 + cn) = p1;
            }
        }
    }
}

// =====================================================================
// Mega combine GEMM: [h | silu | bases] @ [Wc_lstm ; W~] -> partials.
// Split-K x2 (blockIdx.z).
// =====================================================================
__global__ __launch_bounds__(256, 2) void gemm_mega(
    const __half* __restrict__ h16, const __half* __restrict__ actp,
    const __half* __restrict__ wcp, const __half* __restrict__ wtp,
    float* __restrict__ part)
{
    const int kz = blockIdx.z;
    const __half *A0, *A1, *B0, *B1;
    int lda0, lda1, ksA;
    if (kz == 0) {
        A0 = h16; lda0 = 1024; A1 = actp; lda1 = KACT; ksA = 1024;
        B0 = wcp; B1 = wtp;
    } else {
        A0 = nullptr; lda0 = 0; A1 = actp + 4096; lda1 = KACT; ksA = 0;
        B0 = nullptr; B1 = wtp + (size_t)4096 * 1024;
    }
    float* C = part + (size_t)kz * BDIM * 1024;
    const int K = 5120;

    const int tid = threadIdx.x;
    const int lane = tid & 31;
    const int w = tid >> 5;
    const int rowBase = blockIdx.y * 128;
    const int colBase = blockIdx.x * 128;
    const uint32_t sb = smem_u32(smem_h);

    float acc[4][4][4];
#pragma unroll
    for (int i = 0; i < 4; i++)
#pragma unroll
        for (int j = 0; j < 4; j++)
#pragma unroll
            for (int q = 0; q < 4; q++) acc[i][j][q] = 0.0f;

    const int nk = K / BKH;

    auto load_stage = [&](int t, int s) {
        const int kBase = t * BKH;
        const uint32_t sA = sb + s * HSTG;
        const uint32_t sB = sA + HAB;
        const bool lo = kBase < ksA;
        const __half* Ap = lo ? A0 : A1 + (kBase - ksA);
        const int lda = lo ? lda0 : lda1;
        const int ka = lo ? kBase : 0;
        const __half* Bp = lo ? B0 + (size_t)kBase * 1024
                              : B1 + (size_t)(kBase - ksA) * 1024;
#pragma unroll
        for (int i = 0; i < 4; i++) {
            int idx = i * 256 + tid;
            int r = idx >> 3, c = idx & 7;
            cp16(sA + offA(r, c), Ap + (size_t)(rowBase + r) * lda + ka + c * 8);
        }
#pragma unroll
        for (int i = 0; i < 4; i++) {
            int idx = i * 256 + tid;
            int r = idx >> 4, c = idx & 15;
            cp16(sB + offB(r, c), Bp + (size_t)r * 1024 + colBase + c * 8);
        }
    };

#pragma unroll
    for (int s = 0; s < HSSTG - 1; s++) { load_stage(s, s); cp_commit(); }

    const int wm = (w >> 2) * 64;
    const int wn = (w & 3) * 32;
    const int gid = lane >> 2;
    const int tg  = lane & 3;
    const int aRow = lane & 15;
    const int aSel = lane >> 4;
    const int bRow = lane & 15;
    const int bSel = lane >> 4;

    for (int t = 0; t < nk; t++) {
        cp_wait<HSSTG - 2>();
        __syncthreads();
        const int tn = t + HSSTG - 1;
        if (tn < nk) load_stage(tn, tn % HSSTG);
        cp_commit();

        const uint32_t sA = sb + (t % HSSTG) * HSTG;
        const uint32_t sB = sA + HAB;

#pragma unroll
        for (int ks = 0; ks < 4; ks++) {
            uint32_t af[4][4], bf[4][2];
#pragma unroll
            for (int i = 0; i < 4; i++)
                ldmA(af[i], sA + offA(wm + i * 16 + aRow, 2 * ks + aSel));
#pragma unroll
            for (int j2 = 0; j2 < 2; j2++) {
                uint32_t r4[4];
                ldmBT(r4, sB + offB(ks * 16 + bRow, (w & 3) * 4 + j2 * 2 + bSel));
                bf[2 * j2][0] = r4[0]; bf[2 * j2][1] = r4[1];
                bf[2 * j2 + 1][0] = r4[2]; bf[2 * j2 + 1][1] = r4[3];
            }
#pragma unroll
            for (int i = 0; i < 4; i++)
#pragma unroll
                for (int j = 0; j < 4; j++)
                    mma16(acc[i][j], af[i], bf[j]);
        }
    }

#pragma unroll
    for (int i = 0; i < 4; i++) {
        const int r0 = rowBase + wm + i * 16 + gid;
#pragma unroll
        for (int j = 0; j < 4; j++) {
            const int cn = colBase + wn + j * 8 + 2 * tg;
            float2 p0; p0.x = acc[i][j][0]; p0.y = acc[i][j][1];
            float2 p1; p1.x = acc[i][j][2]; p1.y = acc[i][j][3];
            *(float2*)(C + (size_t)r0 * 1024 + cn) = p0;
            *(float2*)(C + (size_t)(r0 + 8) * 1024 + cn) = p1;
        }
    }
}

// out = p0 + p1 + bias
__global__ void add_bias_kernel(const float* __restrict__ part,
                                const float* __restrict__ bias,
                                float* __restrict__ out)
{
    int i = blockIdx.x * 256 + threadIdx.x;
    long e = (long)i * 4;
    int u = (int)(e & 1023);
    float4 a = *(const float4*)(part + e);
    float4 b = *(const float4*)(part + (size_t)BDIM * 1024 + e);
    float4 bs = *(const float4*)(bias + u);
    float4 o;
    o.x = a.x + b.x + bs.x;
    o.y = a.y + b.y + bs.y;
    o.z = a.z + b.z + bs.z;
    o.w = a.w + b.w + bs.w;
    *(float4*)(out + e) = o;
}

// =====================================================================
// Unified prep kernel: all converts + producers in ONE launch.
// blockIdx.x ranges:
//   [0,    2048)  cvt_lstm   (16 e/thr)
//   [2048, 8960)  cvt_kan    (16 e/thr, flat over [9216,3072])
//   [8960, 9984)  cvt_comb   (16 e/thr)
//   [9984, 11008) concat_xh  (16 e/thr)
//   [11008,19200) act        (1 e/thr)
// =====================================================================
__device__ __forceinline__ void cvt8(const float* s, __half* d) {
    float4 v0 = *(const float4*)s;
    float4 v1 = *(const float4*)(s + 4);
    __half2 h[4];
    h[0] = __floats2half2_rn(v0.x, v0.y);
    h[1] = __floats2half2_rn(v0.z, v0.w);
    h[2] = __floats2half2_rn(v1.x, v1.y);
    h[3] = __floats2half2_rn(v1.z, v1.w);
    *(uint4*)d = *(uint4*)h;
}
__device__ __forceinline__ float knot(int j) {
    return -1.0f + 0.4f * (float)(j - 3);
}

__global__ __launch_bounds__(256) void prep_kernel(
    const float* __restrict__ x, const float* __restrict__ h_prev,
    const float* __restrict__ wkf, const float* __restrict__ wrf,
    const float* __restrict__ bw,  const float* __restrict__ sw,
    const float* __restrict__ wcf,
    __half* __restrict__ xh, __half* __restrict__ act,
    __half* __restrict__ wl, __half* __restrict__ wk, __half* __restrict__ wc)
{
    const int bid = blockIdx.x;
    const int tid = threadIdx.x;

    if (bid < 2048) {
        // ---- cvt_lstm: fused [Wk;Wr] [2048,4096] ----
        long e = ((long)bid * 256 + tid) * 16;
        int r = (int)(e >> 12), n = (int)(e & 4095);
        const float* s = (r < 1024) ? wkf + (size_t)r * 4096 + n
                                    : wrf + (size_t)(r - 1024) * 4096 + n;
        cvt8(s, wl + e);
        cvt8(s + 8, wl + e + 8);
    } else if (bid < 8960) {
        // ---- cvt_kan: fused KAN weights [9216,3072] ----
        long e = ((long)(bid - 2048) * 256 + tid) * 16;
        int k = (int)(e / 3072);
        int col = (int)(e - (long)k * 3072);
        int l = col >> 10, u = col & 1023;
        const float* s = (k < 1024)
            ? bw + ((size_t)l * 1024 + k) * 1024 + u
            : sw + ((size_t)l * 8192 + (k - 1024)) * 1024 + u;
        cvt8(s, wk + e);
        cvt8(s + 8, wk + e + 8);
    } else if (bid < 9984) {
        // ---- cvt_comb: [4096,1024] ----
        long e = ((long)(bid - 8960) * 256 + tid) * 16;
        cvt8(wcf + e, wc + e);
        cvt8(wcf + e + 8, wc + e + 8);
    } else if (bid < 11008) {
        // ---- concat_xh: [x | h_prev] -> [2048,2048] ----
        long e = ((long)(bid - 9984) * 256 + tid) * 16;
        int b = (int)(e >> 11), c = (int)(e & 2047);
        const float* src = (c < 1024) ? x + (size_t)b * 1024 + c
                                      : h_prev + (size_t)b * 1024 + (c - 1024);
        cvt8(src, xh + e);
        cvt8(src + 8, xh + e + 8);
    } else {
        // ---- act: silu + bspline bases, 1 elem/thread ----
        int i = (bid - 11008) * 256 + tid;
        int b = i >> 10, d = i & 1023;
        float xv = x[i];
        float s = xv / (1.0f + expf(-xv));

        float bb[11];
#pragma unroll
        for (int j = 0; j < 11; j++)
            bb[j] = (xv >= knot(j) && xv < knot(j + 1)) ? 1.0f : 0.0f;
#pragma unroll
        for (int p = 1; p <= 3; p++) {
            const float invp = 2.5f / (float)p;
#pragma unroll
            for (int j = 0; j <= 10 - p; j++) {
                bb[j] = (xv - knot(j)) * invp * bb[j]
                      + (knot(j + p + 1) - xv) * invp * bb[j + 1];
            }
        }
        __half* row = act + (size_t)b * KACT;
        row[d] = __float2half(s);
        __half2 o[4];
        o[0] = __floats2half2_rn(bb[0], bb[1]);
        o[1] = __floats2half2_rn(bb[2], bb[3]);
        o[2] = __floats2half2_rn(bb[4], bb[5]);
        o[3] = __floats2half2_rn(bb[6], bb[7]);
        *(uint4*)(row + DDIM + d * NB) = *(uint4*)o;
    }
}

// =====================================================================
// Gates
// =====================================================================
__global__ void lstm_gates_kernel(const float* __restrict__ z,
                                  const float* __restrict__ bias,
                                  const float* __restrict__ c_prev,
                                  float* __restrict__ out_h,
                                  float* __restrict__ out_c,
                                  __half* __restrict__ h16)
{
    int i = blockIdx.x * 256 + threadIdx.x;      // per 4 u
    int b = i >> 8, u = (i & 255) * 4;
    const float* zr = z + (size_t)b * 4096;
    float4 zi = *(const float4*)(zr + u);
    float4 zf = *(const float4*)(zr + 1024 + u);
    float4 zg = *(const float4*)(zr + 2048 + u);
    float4 zo = *(const float4*)(zr + 3072 + u);
    float4 bi = *(const float4*)(bias + u);
    float4 bf = *(const float4*)(bias + 1024 + u);
    float4 bg = *(const float4*)(bias + 2048 + u);
    float4 bo = *(const float4*)(bias + 3072 + u);
    float4 cp = *(const float4*)(c_prev + (size_t)b * 1024 + u);

    float hh[4], cc[4];
#pragma unroll
    for (int q = 0; q < 4; q++) {
        float vi = (&zi.x)[q] + (&bi.x)[q];
        float vf = (&zf.x)[q] + (&bf.x)[q];
        float vg = (&zg.x)[q] + (&bg.x)[q];
        float vo = (&zo.x)[q] + (&bo.x)[q];
        float si = 1.0f / (1.0f + expf(-vi));
        float sf = 1.0f / (1.0f + expf(-vf));
        float so = 1.0f / (1.0f + expf(-vo));
        float c = sf * (&cp.x)[q] + si * tanhf(vg);
        hh[q] = so * tanhf(c);
        cc[q] = c;
    }
    float4 ho; ho.x = hh[0]; ho.y = hh[1]; ho.z = hh[2]; ho.w = hh[3];
    float4 co; co.x = cc[0]; co.y = cc[1]; co.z = cc[2]; co.w = cc[3];
    *(float4*)(out_h + (size_t)b * 1024 + u) = ho;
    *(float4*)(out_c + (size_t)b * 1024 + u) = co;
    __half2 hc[2];
    hc[0] = __floats2half2_rn(hh[0], hh[1]);
    hc[1] = __floats2half2_rn(hh[2], hh[3]);
    *(uint2*)(h16 + (size_t)b * 1024 + u) = *(uint2*)hc;
}

// =====================================================================
// Launch
// =====================================================================
extern "C" void kernel_launch(void* const* d_in, const int* in_sizes, int n_in,
                              void* d_out, int out_size)
{
    const float* x       = (const float*)d_in[0];
    const float* h_prev  = (const float*)d_in[1];
    const float* c_prev  = (const float*)d_in[2];
    const float* lstm_k  = (const float*)d_in[3];
    const float* lstm_rk = (const float*)d_in[4];
    const float* lstm_b  = (const float*)d_in[5];
    const float* kan_bw  = (const float*)d_in[6];
    const float* kan_sw  = (const float*)d_in[7];
    const float* comb_w  = (const float*)d_in[8];
    const float* comb_b  = (const float*)d_in[9];

    float* out   = (float*)d_out;
    float* out_h = out + (size_t)BDIM * UDIM;
    float* out_c = out + (size_t)2 * BDIM * UDIM;

    __half *xh, *act, *h16, *wl, *wk, *wc, *wt;
    float* z;
    cudaGetSymbolAddress((void**)&xh,  g_xh);
    cudaGetSymbolAddress((void**)&z,   g_z);
    cudaGetSymbolAddress((void**)&act, g_act);
    cudaGetSymbolAddress((void**)&h16, g_h16);
    cudaGetSymbolAddress((void**)&wl,  g_wl);
    cudaGetSymbolAddress((void**)&wk,  g_wk);
    cudaGetSymbolAddress((void**)&wc,  g_wc);
    cudaGetSymbolAddress((void**)&wt,  g_wt);

    const int DYN = HSSTG * HSTG;   // 98304
    cudaFuncSetAttribute(gemm_fused, cudaFuncAttributeMaxDynamicSharedMemorySize, DYN);
    cudaFuncSetAttribute(gemm_mega,  cudaFuncAttributeMaxDynamicSharedMemorySize, DYN);

    // 1) All conversions + producers in one launch
    prep_kernel<<<19200, 256>>>(x, h_prev, lstm_k, lstm_rk, kan_bw, kan_sw,
                                comb_w, xh, act, wl, wk, wc);

    // 2) Fused W~ + LSTM GEMMs (1088 CTAs; W~ first — longer K)
    gemm_fused<<<1088, 256, DYN>>>(wk, wc, xh, wl, wt, z);

    // 3) Gates (z -> h, c; h fp16 -> g_h16)
    lstm_gates_kernel<<<BDIM * UDIM / 4 / 256, 256>>>(
        z, lstm_b, c_prev, out_h, out_c, h16);

    // 4) Mega combine split-K x2 -> partials in g_z (z dead now)
    gemm_mega<<<dim3(1024 / 128, BDIM / 128, 2), 256, DYN>>>(h16, act, wc, wt, z);

    // 5) out = p0 + p1 + bias
    add_bias_kernel<<<BDIM * 1024 / 4 / 256, 256>>>(z, comb_b, out);
}

// round 11
// speedup vs baseline: 1.6792x; 1.0179x over previous
#include <cuda_runtime.h>
#include <cuda_fp16.h>
#include <cstdint>
#include <math.h>

// ---- Problem constants ----
#define BDIM 2048
#define DDIM 1024
#define UDIM 1024
#define NB   8
#define KACT 9216
#define NCOMB 4096

// ---- Scratch (device globals; no allocation allowed) ----
__device__ __half g_xh[BDIM * 2048];               // [x | h_prev] fp16
__device__ float  g_z[BDIM * 4096];                // LSTM preacts; later mega partials
__device__ __half g_act[(size_t)BDIM * KACT];      // [silu | bases] fp16
__device__ __half g_h16[BDIM * 1024];              // h fp16
__device__ __half g_wl[(size_t)2048 * 4096];       // fused [Wk;Wr]
__device__ __half g_wk[(size_t)KACT * 3072];       // fused KAN weights [9216 x 3072]
__device__ __half g_wc[(size_t)4096 * 1024];       // combine weights fp16
__device__ __half g_wt[(size_t)KACT * 1024];       // W~ = wk @ wc[1024:4096]  [9216 x 1024]

// ---- PTX helpers ----
__device__ __forceinline__ uint32_t smem_u32(const void* p) {
    uint32_t a;
    asm("{ .reg .u64 t; cvta.to.shared.u64 t, %1; cvt.u32.u64 %0, t; }"
        : "=r"(a) : "l"(p));
    return a;
}
__device__ __forceinline__ void cp16(uint32_t s, const void* g) {
    asm volatile("cp.async.cg.shared.global [%0], [%1], 16;" :: "r"(s), "l"(g));
}
__device__ __forceinline__ void cp_commit() {
    asm volatile("cp.async.commit_group;" ::: "memory");
}
template<int N> __device__ __forceinline__ void cp_wait() {
    asm volatile("cp.async.wait_group %0;" :: "n"(N) : "memory");
}
__device__ __forceinline__ void ldmA(uint32_t* r, uint32_t a) {
    asm volatile("ldmatrix.sync.aligned.m8n8.x4.shared.b16 {%0,%1,%2,%3}, [%4];"
                 : "=r"(r[0]), "=r"(r[1]), "=r"(r[2]), "=r"(r[3]) : "r"(a));
}
__device__ __forceinline__ void ldmBT(uint32_t* r, uint32_t a) {
    asm volatile("ldmatrix.sync.aligned.m8n8.x4.trans.shared.b16 {%0,%1,%2,%3}, [%4];"
                 : "=r"(r[0]), "=r"(r[1]), "=r"(r[2]), "=r"(r[3]) : "r"(a));
}
__device__ __forceinline__ void mma16(float* c, const uint32_t* a, const uint32_t* b) {
    asm volatile(
        "mma.sync.aligned.m16n8k16.row.col.f32.f16.f16.f32 "
        "{%0,%1,%2,%3}, {%4,%5,%6,%7}, {%8,%9}, {%0,%1,%2,%3};"
        : "+f"(c[0]), "+f"(c[1]), "+f"(c[2]), "+f"(c[3])
        : "r"(a[0]), "r"(a[1]), "r"(a[2]), "r"(a[3]), "r"(b[0]), "r"(b[1]));
}

#define BKH 64
#define HAB 16384
#define HSTG 32768
#define HSSTG 3

extern __shared__ char smem_h[];

__device__ __forceinline__ uint32_t offA(int r, int c) {
    return (uint32_t)(r * 128 + ((c ^ (r & 7)) << 4));
}
__device__ __forceinline__ uint32_t offB(int k, int c) {
    return (uint32_t)(k * 256 + ((c ^ (k & 7)) << 4));
}

// =====================================================================
// Fused W-tilde + LSTM GEMM launch. 1088 CTAs:
//   bid <  576 : W~  tile (A=wk [9216,3072], B=wc+1024*1024, K=3072, fp16 -> g_wt)
//   bid >= 576 : LSTM tile (A=xh  K=2048, B=wl ldb=4096, fp32 -> z)
// Mainloop: next-stage cp.async issue is peeled into the ks=0 compute slot.
// =====================================================================
__global__ __launch_bounds__(256, 2) void gemm_fused(
    const __half* __restrict__ wkp, const __half* __restrict__ wcp,
    const __half* __restrict__ xhp, const __half* __restrict__ wlp,
    __half* __restrict__ wt, float* __restrict__ z)
{
    const int bid = blockIdx.x;
    const bool isWt = bid < 576;
    const __half *A, *B;
    int lda, ldb, K, rowBase, colBase;
    if (isWt) {
        A = wkp; B = wcp + (size_t)1024 * 1024; lda = 3072; ldb = 1024; K = 3072;
        colBase = (bid & 7) * 128; rowBase = (bid >> 3) * 128;
    } else {
        int b2 = bid - 576;
        A = xhp; B = wlp; lda = 2048; ldb = 4096; K = 2048;
        colBase = (b2 & 31) * 128; rowBase = (b2 >> 5) * 128;
    }

    const int tid = threadIdx.x;
    const int lane = tid & 31;
    const int w = tid >> 5;
    const uint32_t sb = smem_u32(smem_h);

    float acc[4][4][4];
#pragma unroll
    for (int i = 0; i < 4; i++)
#pragma unroll
        for (int j = 0; j < 4; j++)
#pragma unroll
            for (int q = 0; q < 4; q++) acc[i][j][q] = 0.0f;

    const int nk = K / BKH;

    auto load_stage = [&](int t, int s) {
        const int kBase = t * BKH;
        const uint32_t sA = sb + s * HSTG;
        const uint32_t sB = sA + HAB;
#pragma unroll
        for (int i = 0; i < 4; i++) {
            int idx = i * 256 + tid;
            int r = idx >> 3, c = idx & 7;
            cp16(sA + offA(r, c), A + (size_t)(rowBase + r) * lda + kBase + c * 8);
        }
#pragma unroll
        for (int i = 0; i < 4; i++) {
            int idx = i * 256 + tid;
            int r = idx >> 4, c = idx & 15;
            cp16(sB + offB(r, c), B + (size_t)(kBase + r) * ldb + colBase + c * 8);
        }
    };

#pragma unroll
    for (int s = 0; s < HSSTG - 1; s++) { load_stage(s, s); cp_commit(); }

    const int wm = (w >> 2) * 64;
    const int wn = (w & 3) * 32;
    const int gid = lane >> 2;
    const int tg  = lane & 3;
    const int aRow = lane & 15;
    const int aSel = lane >> 4;
    const int bRow = lane & 15;
    const int bSel = lane >> 4;

    for (int t = 0; t < nk; t++) {
        cp_wait<HSSTG - 2>();
        __syncthreads();

        const uint32_t sA = sb + (t % HSSTG) * HSTG;
        const uint32_t sB = sA + HAB;

#pragma unroll
        for (int ks = 0; ks < 4; ks++) {
            uint32_t af[4][4], bf[4][2];
#pragma unroll
            for (int i = 0; i < 4; i++)
                ldmA(af[i], sA + offA(wm + i * 16 + aRow, 2 * ks + aSel));
#pragma unroll
            for (int j2 = 0; j2 < 2; j2++) {
                uint32_t r4[4];
                ldmBT(r4, sB + offB(ks * 16 + bRow, (w & 3) * 4 + j2 * 2 + bSel));
                bf[2 * j2][0] = r4[0]; bf[2 * j2][1] = r4[1];
                bf[2 * j2 + 1][0] = r4[2]; bf[2 * j2 + 1][1] = r4[3];
            }
#pragma unroll
            for (int i = 0; i < 4; i++)
#pragma unroll
                for (int j = 0; j < 4; j++)
                    mma16(acc[i][j], af[i], bf[j]);
            if (ks == 0) {
                const int tn = t + HSSTG - 1;
                if (tn < nk) load_stage(tn, tn % HSSTG);
                cp_commit();
            }
        }
    }

    // ---- epilogue ----
#pragma unroll
    for (int i = 0; i < 4; i++) {
        const int r0 = rowBase + wm + i * 16 + gid;
#pragma unroll
        for (int j = 0; j < 4; j++) {
            const int cn = colBase + wn + j * 8 + 2 * tg;
            float v0 = acc[i][j][0], v1 = acc[i][j][1];
            float v2 = acc[i][j][2], v3 = acc[i][j][3];
            if (isWt) {
                *(__half2*)(wt + (size_t)r0 * 1024 + cn) = __floats2half2_rn(v0, v1);
                *(__half2*)(wt + (size_t)(r0 + 8) * 1024 + cn) = __floats2half2_rn(v2, v3);
            } else {
                float2 p0; p0.x = v0; p0.y = v1;
                float2 p1; p1.x = v2; p1.y = v3;
                *(float2*)(z + (size_t)r0 * 4096 + cn) = p0;
                *(float2*)(z + (size_t)(r0 + 8) * 4096 + cn) = p1;
            }
        }
    }
}

// =====================================================================
// Mega combine GEMM: [h | silu | bases] @ [Wc_lstm ; W~] -> partials.
// Split-K x2 (blockIdx.z). Same peeled-load mainloop.
// =====================================================================
__global__ __launch_bounds__(256, 2) void gemm_mega(
    const __half* __restrict__ h16, const __half* __restrict__ actp,
    const __half* __restrict__ wcp, const __half* __restrict__ wtp,
    float* __restrict__ part)
{
    const int kz = blockIdx.z;
    const __half *A0, *A1, *B0, *B1;
    int lda0, lda1, ksA;
    if (kz == 0) {
        A0 = h16; lda0 = 1024; A1 = actp; lda1 = KACT; ksA = 1024;
        B0 = wcp; B1 = wtp;
    } else {
        A0 = nullptr; lda0 = 0; A1 = actp + 4096; lda1 = KACT; ksA = 0;
        B0 = nullptr; B1 = wtp + (size_t)4096 * 1024;
    }
    float* C = part + (size_t)kz * BDIM * 1024;
    const int K = 5120;

    const int tid = threadIdx.x;
    const int lane = tid & 31;
    const int w = tid >> 5;
    const int rowBase = blockIdx.y * 128;
    const int colBase = blockIdx.x * 128;
    const uint32_t sb = smem_u32(smem_h);

    float acc[4][4][4];
#pragma unroll
    for (int i = 0; i < 4; i++)
#pragma unroll
        for (int j = 0; j < 4; j++)
#pragma unroll
            for (int q = 0; q < 4; q++) acc[i][j][q] = 0.0f;

    const int nk = K / BKH;

    auto load_stage = [&](int t, int s) {
        const int kBase = t * BKH;
        const uint32_t sA = sb + s * HSTG;
        const uint32_t sB = sA + HAB;
        const bool lo = kBase < ksA;
        const __half* Ap = lo ? A0 : A1 + (kBase - ksA);
        const int lda = lo ? lda0 : lda1;
        const int ka = lo ? kBase : 0;
        const __half* Bp = lo ? B0 + (size_t)kBase * 1024
                              : B1 + (size_t)(kBase - ksA) * 1024;
#pragma unroll
        for (int i = 0; i < 4; i++) {
            int idx = i * 256 + tid;
            int r = idx >> 3, c = idx & 7;
            cp16(sA + offA(r, c), Ap + (size_t)(rowBase + r) * lda + ka + c * 8);
        }
#pragma unroll
        for (int i = 0; i < 4; i++) {
            int idx = i * 256 + tid;
            int r = idx >> 4, c = idx & 15;
            cp16(sB + offB(r, c), Bp + (size_t)r * 1024 + colBase + c * 8);
        }
    };

#pragma unroll
    for (int s = 0; s < HSSTG - 1; s++) { load_stage(s, s); cp_commit(); }

    const int wm = (w >> 2) * 64;
    const int wn = (w & 3) * 32;
    const int gid = lane >> 2;
    const int tg  = lane & 3;
    const int aRow = lane & 15;
    const int aSel = lane >> 4;
    const int bRow = lane & 15;
    const int bSel = lane >> 4;

    for (int t = 0; t < nk; t++) {
        cp_wait<HSSTG - 2>();
        __syncthreads();

        const uint32_t sA = sb + (t % HSSTG) * HSTG;
        const uint32_t sB = sA + HAB;

#pragma unroll
        for (int ks = 0; ks < 4; ks++) {
            uint32_t af[4][4], bf[4][2];
#pragma unroll
            for (int i = 0; i < 4; i++)
                ldmA(af[i], sA + offA(wm + i * 16 + aRow, 2 * ks + aSel));
#pragma unroll
            for (int j2 = 0; j2 < 2; j2++) {
                uint32_t r4[4];
                ldmBT(r4, sB + offB(ks * 16 + bRow, (w & 3) * 4 + j2 * 2 + bSel));
                bf[2 * j2][0] = r4[0]; bf[2 * j2][1] = r4[1];
                bf[2 * j2 + 1][0] = r4[2]; bf[2 * j2 + 1][1] = r4[3];
            }
#pragma unroll
            for (int i = 0; i < 4; i++)
#pragma unroll
                for (int j = 0; j < 4; j++)
                    mma16(acc[i][j], af[i], bf[j]);
            if (ks == 0) {
                const int tn = t + HSSTG - 1;
                if (tn < nk) load_stage(tn, tn % HSSTG);
                cp_commit();
            }
        }
    }

#pragma unroll
    for (int i = 0; i < 4; i++) {
        const int r0 = rowBase + wm + i * 16 + gid;
#pragma unroll
        for (int j = 0; j < 4; j++) {
            const int cn = colBase + wn + j * 8 + 2 * tg;
            float2 p0; p0.x = acc[i][j][0]; p0.y = acc[i][j][1];
            float2 p1; p1.x = acc[i][j][2]; p1.y = acc[i][j][3];
            *(float2*)(C + (size_t)r0 * 1024 + cn) = p0;
            *(float2*)(C + (size_t)(r0 + 8) * 1024 + cn) = p1;
        }
    }
}

// out = p0 + p1 + bias
__global__ void add_bias_kernel(const float* __restrict__ part,
                                const float* __restrict__ bias,
                                float* __restrict__ out)
{
    int i = blockIdx.x * 256 + threadIdx.x;
    long e = (long)i * 4;
    int u = (int)(e & 1023);
    float4 a = *(const float4*)(part + e);
    float4 b = *(const float4*)(part + (size_t)BDIM * 1024 + e);
    float4 bs = *(const float4*)(bias + u);
    float4 o;
    o.x = a.x + b.x + bs.x;
    o.y = a.y + b.y + bs.y;
    o.z = a.z + b.z + bs.z;
    o.w = a.w + b.w + bs.w;
    *(float4*)(out + e) = o;
}

// =====================================================================
// Unified prep kernel
// =====================================================================
__device__ __forceinline__ void cvt8(const float* s, __half* d) {
    float4 v0 = *(const float4*)s;
    float4 v1 = *(const float4*)(s + 4);
    __half2 h[4];
    h[0] = __floats2half2_rn(v0.x, v0.y);
    h[1] = __floats2half2_rn(v0.z, v0.w);
    h[2] = __floats2half2_rn(v1.x, v1.y);
    h[3] = __floats2half2_rn(v1.z, v1.w);
    *(uint4*)d = *(uint4*)h;
}
__device__ __forceinline__ float knot(int j) {
    return -1.0f + 0.4f * (float)(j - 3);
}

__global__ __launch_bounds__(256) void prep_kernel(
    const float* __restrict__ x, const float* __restrict__ h_prev,
    const float* __restrict__ wkf, const float* __restrict__ wrf,
    const float* __restrict__ bw,  const float* __restrict__ sw,
    const float* __restrict__ wcf,
    __half* __restrict__ xh, __half* __restrict__ act,
    __half* __restrict__ wl, __half* __restrict__ wk, __half* __restrict__ wc)
{
    const int bid = blockIdx.x;
    const int tid = threadIdx.x;

    if (bid < 2048) {
        long e = ((long)bid * 256 + tid) * 16;
        int r = (int)(e >> 12), n = (int)(e & 4095);
        const float* s = (r < 1024) ? wkf + (size_t)r * 4096 + n
                                    : wrf + (size_t)(r - 1024) * 4096 + n;
        cvt8(s, wl + e);
        cvt8(s + 8, wl + e + 8);
    } else if (bid < 8960) {
        long e = ((long)(bid - 2048) * 256 + tid) * 16;
        int k = (int)(e / 3072);
        int col = (int)(e - (long)k * 3072);
        int l = col >> 10, u = col & 1023;
        const float* s = (k < 1024)
            ? bw + ((size_t)l * 1024 + k) * 1024 + u
            : sw + ((size_t)l * 8192 + (k - 1024)) * 1024 + u;
        cvt8(s, wk + e);
        cvt8(s + 8, wk + e + 8);
    } else if (bid < 9984) {
        long e = ((long)(bid - 8960) * 256 + tid) * 16;
        cvt8(wcf + e, wc + e);
        cvt8(wcf + e + 8, wc + e + 8);
    } else if (bid < 11008) {
        long e = ((long)(bid - 9984) * 256 + tid) * 16;
        int b = (int)(e >> 11), c = (int)(e & 2047);
        const float* src = (c < 1024) ? x + (size_t)b * 1024 + c
                                      : h_prev + (size_t)b * 1024 + (c - 1024);
        cvt8(src, xh + e);
        cvt8(src + 8, xh + e + 8);
    } else {
        int i = (bid - 11008) * 256 + tid;
        int b = i >> 10, d = i & 1023;
        float xv = x[i];
        float s = xv / (1.0f + expf(-xv));

        float bb[11];
#pragma unroll
        for (int j = 0; j < 11; j++)
            bb[j] = (xv >= knot(j) && xv < knot(j + 1)) ? 1.0f : 0.0f;
#pragma unroll
        for (int p = 1; p <= 3; p++) {
            const float invp = 2.5f / (float)p;
#pragma unroll
            for (int j = 0; j <= 10 - p; j++) {
                bb[j] = (xv - knot(j)) * invp * bb[j]
                      + (knot(j + p + 1) - xv) * invp * bb[j + 1];
            }
        }
        __half* row = act + (size_t)b * KACT;
        row[d] = __float2half(s);
        __half2 o[4];
        o[0] = __floats2half2_rn(bb[0], bb[1]);
        o[1] = __floats2half2_rn(bb[2], bb[3]);
        o[2] = __floats2half2_rn(bb[4], bb[5]);
        o[3] = __floats2half2_rn(bb[6], bb[7]);
        *(uint4*)(row + DDIM + d * NB) = *(uint4*)o;
    }
}

// =====================================================================
// Gates
// =====================================================================
__global__ void lstm_gates_kernel(const float* __restrict__ z,
                                  const float* __restrict__ bias,
                                  const float* __restrict__ c_prev,
                                  float* __restrict__ out_h,
                                  float* __restrict__ out_c,
                                  __half* __restrict__ h16)
{
    int i = blockIdx.x * 256 + threadIdx.x;      // per 4 u
    int b = i >> 8, u = (i & 255) * 4;
    const float* zr = z + (size_t)b * 4096;
    float4 zi = *(const float4*)(zr + u);
    float4 zf = *(const float4*)(zr + 1024 + u);
    float4 zg = *(const float4*)(zr + 2048 + u);
    float4 zo = *(const float4*)(zr + 3072 + u);
    float4 bi = *(const float4*)(bias + u);
    float4 bf = *(const float4*)(bias + 1024 + u);
    float4 bg = *(const float4*)(bias + 2048 + u);
    float4 bo = *(const float4*)(bias + 3072 + u);
    float4 cp = *(const float4*)(c_prev + (size_t)b * 1024 + u);

    float hh[4], cc[4];
#pragma unroll
    for (int q = 0; q < 4; q++) {
        float vi = (&zi.x)[q] + (&bi.x)[q];
        float vf = (&zf.x)[q] + (&bf.x)[q];
        float vg = (&zg.x)[q] + (&bg.x)[q];
        float vo = (&zo.x)[q] + (&bo.x)[q];
        float si = 1.0f / (1.0f + expf(-vi));
        float sf = 1.0f / (1.0f + expf(-vf));
        float so = 1.0f / (1.0f + expf(-vo));
        float c = sf * (&cp.x)[q] + si * tanhf(vg);
        hh[q] = so * tanhf(c);
        cc[q] = c;
    }
    float4 ho; ho.x = hh[0]; ho.y = hh[1]; ho.z = hh[2]; ho.w = hh[3];
    float4 co; co.x = cc[0]; co.y = cc[1]; co.z = cc[2]; co.w = cc[3];
    *(float4*)(out_h + (size_t)b * 1024 + u) = ho;
    *(float4*)(out_c + (size_t)b * 1024 + u) = co;
    __half2 hc[2];
    hc[0] = __floats2half2_rn(hh[0], hh[1]);
    hc[1] = __floats2half2_rn(hh[2], hh[3]);
    *(uint2*)(h16 + (size_t)b * 1024 + u) = *(uint2*)hc;
}

// =====================================================================
// Launch
// =====================================================================
extern "C" void kernel_launch(void* const* d_in, const int* in_sizes, int n_in,
                              void* d_out, int out_size)
{
    const float* x       = (const float*)d_in[0];
    const float* h_prev  = (const float*)d_in[1];
    const float* c_prev  = (const float*)d_in[2];
    const float* lstm_k  = (const float*)d_in[3];
    const float* lstm_rk = (const float*)d_in[4];
    const float* lstm_b  = (const float*)d_in[5];
    const float* kan_bw  = (const float*)d_in[6];
    const float* kan_sw  = (const float*)d_in[7];
    const float* comb_w  = (const float*)d_in[8];
    const float* comb_b  = (const float*)d_in[9];

    float* out   = (float*)d_out;
    float* out_h = out + (size_t)BDIM * UDIM;
    float* out_c = out + (size_t)2 * BDIM * UDIM;

    __half *xh, *act, *h16, *wl, *wk, *wc, *wt;
    float* z;
    cudaGetSymbolAddress((void**)&xh,  g_xh);
    cudaGetSymbolAddress((void**)&z,   g_z);
    cudaGetSymbolAddress((void**)&act, g_act);
    cudaGetSymbolAddress((void**)&h16, g_h16);
    cudaGetSymbolAddress((void**)&wl,  g_wl);
    cudaGetSymbolAddress((void**)&wk,  g_wk);
    cudaGetSymbolAddress((void**)&wc,  g_wc);
    cudaGetSymbolAddress((void**)&wt,  g_wt);

    const int DYN = HSSTG * HSTG;   // 98304
    cudaFuncSetAttribute(gemm_fused, cudaFuncAttributeMaxDynamicSharedMemorySize, DYN);
    cudaFuncSetAttribute(gemm_mega,  cudaFuncAttributeMaxDynamicSharedMemorySize, DYN);

    // 1) All conversions + producers in one launch
    prep_kernel<<<19200, 256>>>(x, h_prev, lstm_k, lstm_rk, kan_bw, kan_sw,
                                comb_w, xh, act, wl, wk, wc);

    // 2) Fused W~ + LSTM GEMMs (1088 CTAs; W~ first — longer K)
    gemm_fused<<<1088, 256, DYN>>>(wk, wc, xh, wl, wt, z);

    // 3) Gates (z -> h, c; h fp16 -> g_h16)
    lstm_gates_kernel<<<BDIM * UDIM / 4 / 256, 256>>>(
        z, lstm_b, c_prev, out_h, out_c, h16);

    // 4) Mega combine split-K x2 -> partials in g_z (z dead now)
    gemm_mega<<<dim3(1024 / 128, BDIM / 128, 2), 256, DYN>>>(h16, act, wc, wt, z);

    // 5) out = p0 + p1 + bias
    add_bias_kernel<<<BDIM * 1024 / 4 / 256, 256>>>(z, comb_b, out);
}